// round 11
// baseline (speedup 1.0000x reference)
#include <cuda_runtime.h>
#include <cuda_fp16.h>
#include <math.h>

typedef unsigned long long ull;

// Problem constants: B=64, S=512, D=64, H=128, HEADS=4, HD=32, I=13, A=3

// -------- scratch (device globals; no allocation) --------
__device__ float g_Gx[32768 * 512];        // x-part of gates + b_cell
__device__ float g_seqh[32768 * 128];      // (b,s,h)
__device__ float g_qkv[32768 * 384 + 64];  // (b,s, q|k|v)
__device__ float g_av[32768 * 128];        // (b,s, head*32+d)
__device__ float g_attnout[32768 * 128];
__device__ float g_ctx[64 * 128];          // sum over s of LN rows

// ---- packed f32x2 helpers ----
__device__ __forceinline__ ull pk2(float a, float b) {
    ull r; asm("mov.b64 %0,{%1,%2};" : "=l"(r) : "f"(a), "f"(b)); return r;
}
__device__ __forceinline__ ull fma2(ull a, ull b, ull c) {
    ull d; asm("fma.rn.f32x2 %0,%1,%2,%3;" : "=l"(d) : "l"(a), "l"(b), "l"(c)); return d;
}
__device__ __forceinline__ ull mul2(ull a, ull b) {
    ull d; asm("mul.rn.f32x2 %0,%1,%2;" : "=l"(d) : "l"(a), "l"(b)); return d;
}
__device__ __forceinline__ float2 up2(ull v) {
    float2 f; asm("mov.b64 {%0,%1},%2;" : "=f"(f.x), "=f"(f.y) : "l"(v)); return f;
}

// ============================================================
// Generic batched NT GEMM: 64xBN tile, 4x4 thread tile, TK=32,
// register double-buffer prefetch of the next k-tile.
// C[m,n] = alpha*sum_k A[m,k]*B[n,k] + bias[n]
// ============================================================
template <int BN>
__global__ void gemm_nt_flex(
    const float* __restrict__ A, int Am, long long zA1, int zA2,
    const float* __restrict__ B, int Bn, int Bk, long long zB1, int zB2,
    const float* __restrict__ bias,
    float* __restrict__ C, int Cld, long long zC1, int zC2,
    int M, int N, int K, float alpha)
{
    constexpr int TM = 64, TK = 32;
    constexpr int TX = BN / 4;            // 16
    constexpr int TPB = TX * 16;          // 256
    constexpr int NA = TM * TK / TPB;     // 8
    constexpr int NB = BN * TK / TPB;     // 8
    __shared__ float As[TK][TM + 4];
    __shared__ float Bs[TK][BN + 4];

    int z = blockIdx.z;
    const float* Ab = A + (long long)(z >> 2) * zA1 + (long long)(z & 3) * zA2;
    const float* Bb = B + (long long)(z >> 2) * zB1 + (long long)(z & 3) * zB2;
    float* Cb = C + (long long)(z >> 2) * zC1 + (long long)(z & 3) * zC2;

    int tid = threadIdx.x;
    int tx = tid % TX, ty = tid / TX;
    int m0 = blockIdx.y * TM, n0 = blockIdx.x * BN;

    float aR[NA], bR[NB];

    // prefetch k-tile 0
#pragma unroll
    for (int j = 0; j < NA; j++) {
        int i = tid + j * TPB; int m = i >> 5, k = i & 31;
        aR[j] = Ab[(long long)(m0 + m) * Am + k];
    }
    if (Bk == 1) {
#pragma unroll
        for (int j = 0; j < NB; j++) {
            int i = tid + j * TPB; int n = i >> 5, k = i & 31;
            bR[j] = (n0 + n < N) ? Bb[(long long)(n0 + n) * Bn + k] : 0.f;
        }
    } else {
#pragma unroll
        for (int j = 0; j < NB; j++) {
            int i = tid + j * TPB; int n = i % BN, k = i / BN;
            bR[j] = (n0 + n < N) ? Bb[(long long)(n0 + n) * Bn + (long long)k * Bk] : 0.f;
        }
    }

    ull acc2[4][2] = {};
    for (int k0 = 0; k0 < K; k0 += TK) {
        // store current fragments to smem
#pragma unroll
        for (int j = 0; j < NA; j++) {
            int i = tid + j * TPB; int m = i >> 5, k = i & 31;
            As[k][m] = aR[j];
        }
        if (Bk == 1) {
#pragma unroll
            for (int j = 0; j < NB; j++) {
                int i = tid + j * TPB; int n = i >> 5, k = i & 31;
                Bs[k][n] = bR[j];
            }
        } else {
#pragma unroll
            for (int j = 0; j < NB; j++) {
                int i = tid + j * TPB; int n = i % BN, k = i / BN;
                Bs[k][n] = bR[j];
            }
        }
        __syncthreads();

        // prefetch next k-tile (latency hidden by compute below)
        int k1 = k0 + TK;
        if (k1 < K) {
#pragma unroll
            for (int j = 0; j < NA; j++) {
                int i = tid + j * TPB; int m = i >> 5, k = i & 31;
                aR[j] = Ab[(long long)(m0 + m) * Am + k1 + k];
            }
            if (Bk == 1) {
#pragma unroll
                for (int j = 0; j < NB; j++) {
                    int i = tid + j * TPB; int n = i >> 5, k = i & 31;
                    bR[j] = (n0 + n < N) ? Bb[(long long)(n0 + n) * Bn + k1 + k] : 0.f;
                }
            } else {
#pragma unroll
                for (int j = 0; j < NB; j++) {
                    int i = tid + j * TPB; int n = i % BN, k = i / BN;
                    bR[j] = (n0 + n < N) ? Bb[(long long)(n0 + n) * Bn + (long long)(k1 + k) * Bk] : 0.f;
                }
            }
        }

#pragma unroll
        for (int kk = 0; kk < TK; kk++) {
            float4 a4 = *(const float4*)&As[kk][ty * 4];
            float4 b4 = *(const float4*)&Bs[kk][tx * 4];
            ull bp0 = pk2(b4.x, b4.y), bp1 = pk2(b4.z, b4.w);
            float a[4] = {a4.x, a4.y, a4.z, a4.w};
#pragma unroll
            for (int i = 0; i < 4; i++) {
                ull aa = pk2(a[i], a[i]);
                acc2[i][0] = fma2(aa, bp0, acc2[i][0]);
                acc2[i][1] = fma2(aa, bp1, acc2[i][1]);
            }
        }
        __syncthreads();
    }
#pragma unroll
    for (int i = 0; i < 4; i++) {
        long long m = m0 + ty * 4 + i;
#pragma unroll
        for (int jp = 0; jp < 2; jp++) {
            float2 f = up2(acc2[i][jp]);
            int n = n0 + tx * 4 + 2 * jp;
            if (n < N)     Cb[m * Cld + n]     = alpha * f.x + (bias ? bias[n] : 0.f);
            if (n + 1 < N) Cb[m * Cld + n + 1] = alpha * f.y + (bias ? bias[n + 1] : 0.f);
        }
    }
}

// ============================================================
// Sequential sLSTM scan: 96 weights in regs (f32x2 pairs), 32 in smem.
// Fast-math nonlinear tail (MUFU-based exp/tanh/div).
// ============================================================
__global__ void __launch_bounds__(512, 1)
scan_kernel(const float* __restrict__ Wcell, const float* __restrict__ Gx,
            float* __restrict__ seqh)
{
    extern __shared__ float2 ws2[];  // [16][512]
    __shared__ float h_s[128], c_s[128], n_s[128], gates_s[512];
    int tid = threadIdx.x, b = blockIdx.x;

    ull wr2[48];
    {
        const float4* wrow = (const float4*)(Wcell + tid * 192 + 64);
#pragma unroll
        for (int c = 0; c < 24; c++) {
            float4 w = wrow[c];
            wr2[2 * c] = pk2(w.x, w.y);
            wr2[2 * c + 1] = pk2(w.z, w.w);
        }
    }
#pragma unroll
    for (int p = 0; p < 16; p++)
        ws2[p * 512 + tid] = make_float2(Wcell[tid * 192 + 160 + 2 * p],
                                         Wcell[tid * 192 + 160 + 2 * p + 1]);
    if (tid < 128) { h_s[tid] = 0.f; c_s[tid] = 0.f; n_s[tid] = 1.f; }
    __syncthreads();

    long long gbase = (long long)b * 512 * 512 + tid;
    long long hbase = (long long)b * 512 * 128;
    float gx = Gx[gbase];

    for (int t = 0; t < 512; t++) {
        float gx_next = (t < 511) ? Gx[gbase + (long long)(t + 1) * 512] : 0.f;
        ull a0 = pk2(gx, 0.f), a1 = pk2(0.f, 0.f);
#pragma unroll
        for (int c = 0; c < 24; c++) {
            float4 h4 = *(const float4*)&h_s[c * 4];
            a0 = fma2(wr2[2 * c],     pk2(h4.x, h4.y), a0);
            a1 = fma2(wr2[2 * c + 1], pk2(h4.z, h4.w), a1);
        }
#pragma unroll
        for (int c = 0; c < 8; c++) {
            float4 h4 = *(const float4*)&h_s[96 + c * 4];
            ull wA = *(const ull*)&ws2[(2 * c) * 512 + tid];
            ull wB = *(const ull*)&ws2[(2 * c + 1) * 512 + tid];
            a0 = fma2(wA, pk2(h4.x, h4.y), a0);
            a1 = fma2(wB, pk2(h4.z, h4.w), a1);
        }
        float2 f0 = up2(a0), f1 = up2(a1);
        gates_s[tid] = (f0.x + f0.y) + (f1.x + f1.y);
        __syncthreads();
        if (tid < 128) {
            float gi = gates_s[tid], gf = gates_s[tid + 128];
            float go = gates_s[tid + 256], gz = gates_s[tid + 384];
            float ii = __expf(fminf(fmaxf(gi, -5.f), 5.f));
            float ff = __expf(fminf(fmaxf(gf, -5.f), 5.f));
            float cc = fmaf(ff, c_s[tid], ii * __tanhf(gz));
            cc = fminf(fmaxf(cc, -1e6f), 1e6f);
            float nn = fminf(fmaxf(fmaf(ff, n_s[tid], ii), 1e-6f), 1e6f);
            float sig = __frcp_rn(1.f + __expf(-go));
            float hh = __fdividef(cc, nn) * sig;
            if (!isfinite(hh)) hh = 0.f;
            c_s[tid] = cc; n_s[tid] = nn; h_s[tid] = hh;
            seqh[hbase + (long long)t * 128 + tid] = hh;
        }
        __syncthreads();
        gx = gx_next;
    }
}

// ============================================================
// Fused flash attention v5 (R8/R10 version): 256 threads, 3 CTAs/SM.
// K/V streamed from gmem (L2) in 64-k chunks; Q + P + stats in smem.
// ============================================================
__global__ void __launch_bounds__(256, 3)
flash_kernel(const float* __restrict__ qkv, float* __restrict__ av)
{
    extern __shared__ float sm[];
    float* Qs   = sm;             // [32][132]  4224 (q transposed, pre-scaled)
    float* Ks   = sm + 4224;      // [32][68]   2176 (k chunk transposed)
    float* Vs   = sm + 6400;      // [64][36]   2304 (v chunk row-major)
    float* Ps   = sm + 8704;      // [128][68]  8704
    float* rowM = sm + 17408;     // [128]
    float* rowL = sm + 17536;     // [128]
    float* rowS = sm + 17664;     // [128]  (total 17792 floats = 71168 B)

    int tid = threadIdx.x;
    int qt = blockIdx.x, bh = blockIdx.y;
    int b = bh >> 2, h = bh & 3;
    long long base = (long long)b * 512 * 384 + h * 32;
    int q0 = qt * 128;
    const float alpha = 0.17677669529663687f;

    // -------- stage Q (scaled, transposed) --------
    for (int idx = tid; idx < 128 * 8; idx += 256) {
        int s = idx >> 3, dg = idx & 7;
        float4 v = *(const float4*)&qkv[base + (long long)(q0 + s) * 384 + dg * 4];
        Qs[(dg * 4 + 0) * 132 + s] = v.x * alpha;
        Qs[(dg * 4 + 1) * 132 + s] = v.y * alpha;
        Qs[(dg * 4 + 2) * 132 + s] = v.z * alpha;
        Qs[(dg * 4 + 3) * 132 + s] = v.w * alpha;
    }
    if (tid < 128) { rowM[tid] = -1e30f; rowL[tid] = 0.f; }

    // QK mapping
    int w = tid >> 5, l = tid & 31;
    int lq = l >> 4, lk = l & 15;        // lq 0..1, lk 0..15
    int qrow0 = w * 16 + lq * 8;         // 8 consecutive q
    int kcol0 = lk * 4;                  // 4 consecutive k within chunk
    // PV mapping
    int qg = tid >> 3;                   // q rows {qg, qg+32, qg+64, qg+96}
    int dg = tid & 7;                    // d = 4*dg
    ull out[4][2];
#pragma unroll
    for (int i = 0; i < 4; i++) { out[i][0] = 0ULL; out[i][1] = 0ULL; }

    for (int kt = 0; kt < 8; kt++) {
        int kbase = kt * 64;
        // ---- stage K (transposed) and V (row-major) chunk from gmem/L2 ----
        for (int idx = tid; idx < 64 * 8; idx += 256) {
            int s = idx >> 3, dgi = idx & 7;
            long long grow = base + (long long)(kbase + s) * 384 + dgi * 4;
            float4 kv = *(const float4*)&qkv[grow + 128];
            Ks[(dgi * 4 + 0) * 68 + s] = kv.x;
            Ks[(dgi * 4 + 1) * 68 + s] = kv.y;
            Ks[(dgi * 4 + 2) * 68 + s] = kv.z;
            Ks[(dgi * 4 + 3) * 68 + s] = kv.w;
            float4 vv = *(const float4*)&qkv[grow + 256];
            *(float4*)&Vs[s * 36 + dgi * 4] = vv;
        }
        __syncthreads();

        // ---- QK: acc[8q][2 pairs] ----
        ull acc[8][2];
#pragma unroll
        for (int qi = 0; qi < 8; qi++) { acc[qi][0] = 0ULL; acc[qi][1] = 0ULL; }

#pragma unroll 2
        for (int d = 0; d < 32; d++) {
            float4 kf = *(const float4*)&Ks[d * 68 + kcol0];
            ull kp0 = pk2(kf.x, kf.y), kp1 = pk2(kf.z, kf.w);
            float4 qa = *(const float4*)&Qs[d * 132 + qrow0];
            float4 qb = *(const float4*)&Qs[d * 132 + qrow0 + 4];
            float qv[8] = {qa.x, qa.y, qa.z, qa.w, qb.x, qb.y, qb.z, qb.w};
#pragma unroll
            for (int qi = 0; qi < 8; qi++) {
                ull qq = pk2(qv[qi], qv[qi]);
                acc[qi][0] = fma2(qq, kp0, acc[qi][0]);
                acc[qi][1] = fma2(qq, kp1, acc[qi][1]);
            }
        }
        // ---- online softmax: each row fully inside this warp (16 lk lanes) ----
#pragma unroll
        for (int qi = 0; qi < 8; qi++) {
            float2 fa = up2(acc[qi][0]), fb = up2(acc[qi][1]);
            float p0 = fa.x, p1 = fa.y, p2 = fb.x, p3 = fb.y;
            int q = qrow0 + qi;
            float m_old = rowM[q];
            float tmax = fmaxf(fmaxf(p0, p1), fmaxf(p2, p3));
#pragma unroll
            for (int off = 1; off < 16; off <<= 1)
                tmax = fmaxf(tmax, __shfl_xor_sync(0xffffffffu, tmax, off));
            float mnew = fmaxf(m_old, tmax);
            p0 = __expf(p0 - mnew); p1 = __expf(p1 - mnew);
            p2 = __expf(p2 - mnew); p3 = __expf(p3 - mnew);
            float tsum = (p0 + p1) + (p2 + p3);
#pragma unroll
            for (int off = 1; off < 16; off <<= 1)
                tsum += __shfl_xor_sync(0xffffffffu, tsum, off);
            if (lk == 0) {
                float sc = __expf(m_old - mnew);
                rowS[q] = sc; rowM[q] = mnew;
                rowL[q] = rowL[q] * sc + tsum;
            }
            *(float4*)&Ps[q * 68 + kcol0] = make_float4(p0, p1, p2, p3);
        }
        __syncthreads();

        // ---- PV: thread = 4q (strided 32) x 4d ----
#pragma unroll
        for (int i = 0; i < 4; i++) {
            float sc = rowS[qg + 32 * i];
            ull s2 = pk2(sc, sc);
            out[i][0] = mul2(s2, out[i][0]);
            out[i][1] = mul2(s2, out[i][1]);
        }
#pragma unroll 4
        for (int kl = 0; kl < 64; kl += 2) {
            const float* vr = &Vs[kl * 36 + dg * 4];
            float4 v0 = *(const float4*)&vr[0];
            float4 v1 = *(const float4*)&vr[36];
            ull v0a = pk2(v0.x, v0.y), v0b = pk2(v0.z, v0.w);
            ull v1a = pk2(v1.x, v1.y), v1b = pk2(v1.z, v1.w);
#pragma unroll
            for (int i = 0; i < 4; i++) {
                float2 pf = up2(*(const ull*)&Ps[(qg + 32 * i) * 68 + kl]);
                ull pd0 = pk2(pf.x, pf.x), pd1 = pk2(pf.y, pf.y);
                out[i][0] = fma2(pd0, v0a, out[i][0]);
                out[i][1] = fma2(pd0, v0b, out[i][1]);
                out[i][0] = fma2(pd1, v1a, out[i][0]);
                out[i][1] = fma2(pd1, v1b, out[i][1]);
            }
        }
        __syncthreads();
    }
    // ---- finalize ----
#pragma unroll
    for (int i = 0; i < 4; i++) {
        int q = qg + 32 * i;
        float inv = 1.f / rowL[q];
        ull iv = pk2(inv, inv);
        long long orow = (long long)(b * 512 + q0 + q) * 128 + h * 32 + dg * 4;
        *(ull*)&av[orow] = mul2(iv, out[i][0]);
        *(ull*)&av[orow + 2] = mul2(iv, out[i][1]);
    }
}

// ============================================================
// Reductions (128-thread blocks)
// ============================================================
__device__ __forceinline__ float2 blockReduce2(float a, float b, float2* sh)
{
#pragma unroll
    for (int o = 16; o; o >>= 1) {
        a += __shfl_xor_sync(0xffffffffu, a, o);
        b += __shfl_xor_sync(0xffffffffu, b, o);
    }
    int w = threadIdx.x >> 5;
    if ((threadIdx.x & 31) == 0) sh[w] = make_float2(a, b);
    __syncthreads();
    float2 r;
    r.x = sh[0].x + sh[1].x + sh[2].x + sh[3].x;
    r.y = sh[0].y + sh[1].y + sh[2].y + sh[3].y;
    __syncthreads();
    return r;
}

__global__ void zero_ctx_kernel(float* ctx) { ctx[blockIdx.x * 128 + threadIdx.x] = 0.f; }

__global__ void ln_mean_kernel(const float* __restrict__ seqh, const float* __restrict__ ao,
                               const float* __restrict__ g, const float* __restrict__ bln,
                               float* __restrict__ ctx)
{
    __shared__ float2 sh[4];
    int b = blockIdx.x >> 5, chunk = blockIdx.x & 31;
    int tid = threadIdx.x;
    float acc = 0.f;
    for (int r = 0; r < 16; r++) {
        long long row = ((long long)b * 512 + chunk * 16 + r) * 128;
        float y = seqh[row + tid] + ao[row + tid];
        float2 ss = blockReduce2(y, y * y, sh);
        float mean = ss.x * (1.f / 128.f);
        float var = ss.y * (1.f / 128.f) - mean * mean;
        acc += g[tid] * (y - mean) * rsqrtf(var + 1e-5f) + bln[tid];
    }
    atomicAdd(&ctx[b * 128 + tid], acc);
}

__global__ void heads_kernel(const float* __restrict__ ctx, const float* __restrict__ info,
    const float* __restrict__ Wa1, const float* __restrict__ ba1,
    const float* __restrict__ lna_g, const float* __restrict__ lna_b,
    const float* __restrict__ Wa2, const float* __restrict__ ba2,
    const float* __restrict__ Wc1, const float* __restrict__ bc1,
    const float* __restrict__ lnc_g, const float* __restrict__ lnc_b,
    const float* __restrict__ Wc2, const float* __restrict__ bc2,
    float* __restrict__ out)
{
    __shared__ float comb[144];
    __shared__ float ra[128], rc[128];
    __shared__ float logit[3];
    __shared__ float2 sh[4];
    int b = blockIdx.x, tid = threadIdx.x;
    comb[tid] = ctx[b * 128 + tid] * (1.f / 512.f);
    if (tid < 16) comb[128 + tid] = (tid < 13) ? info[b * 13 + tid] : 0.f;
    __syncthreads();

    float sa = ba1[tid], sc = bc1[tid];
    for (int k = 0; k < 141; k++) {
        sa = fmaf(Wa1[tid * 141 + k], comb[k], sa);
        sc = fmaf(Wc1[tid * 141 + k], comb[k], sc);
    }
    float2 r2 = blockReduce2(sa, sa * sa, sh);
    float ma = r2.x * (1.f / 128.f), va = r2.y * (1.f / 128.f) - ma * ma;
    ra[tid] = fmaxf(lna_g[tid] * (sa - ma) * rsqrtf(va + 1e-5f) + lna_b[tid], 0.f);
    r2 = blockReduce2(sc, sc * sc, sh);
    float mc = r2.x * (1.f / 128.f), vc = r2.y * (1.f / 128.f) - mc * mc;
    rc[tid] = fmaxf(lnc_g[tid] * (sc - mc) * rsqrtf(vc + 1e-5f) + lnc_b[tid], 0.f);
    __syncthreads();

    if (tid < 3) {
        float l = ba2[tid];
        for (int k = 0; k < 128; k++) l = fmaf(Wa2[tid * 128 + k], ra[k], l);
        logit[tid] = l;
    }
    float2 vv = blockReduce2(rc[tid] * Wc2[tid], 0.f, sh);
    if (tid == 0) out[192 + b] = vv.x + bc2[0];
    __syncthreads();
    if (tid == 0) {
        float m = fmaxf(logit[0], fmaxf(logit[1], logit[2]));
        float e0 = expf(logit[0] - m), e1 = expf(logit[1] - m), e2 = expf(logit[2] - m);
        float inv = 1.f / (e0 + e1 + e2);
        out[b * 3 + 0] = e0 * inv;
        out[b * 3 + 1] = e1 * inv;
        out[b * 3 + 2] = e2 * inv;
    }
}

// ============================================================
extern "C" void kernel_launch(void* const* d_in, const int* in_sizes, int n_in,
                              void* d_out, int out_size)
{
    const float* x      = (const float*)d_in[0];
    const float* info   = (const float*)d_in[1];
    const float* W_cell = (const float*)d_in[2];
    const float* b_cell = (const float*)d_in[3];
    const float* Wqkv   = (const float*)d_in[4];
    const float* bqkv   = (const float*)d_in[5];
    const float* Wo     = (const float*)d_in[6];
    const float* bo     = (const float*)d_in[7];
    const float* ln_g   = (const float*)d_in[8];
    const float* ln_b   = (const float*)d_in[9];
    const float* Wa1    = (const float*)d_in[10];
    const float* ba1    = (const float*)d_in[11];
    const float* lna_g  = (const float*)d_in[12];
    const float* lna_b  = (const float*)d_in[13];
    const float* Wa2    = (const float*)d_in[14];
    const float* ba2    = (const float*)d_in[15];
    const float* Wc1    = (const float*)d_in[16];
    const float* bc1    = (const float*)d_in[17];
    const float* lnc_g  = (const float*)d_in[18];
    const float* lnc_b  = (const float*)d_in[19];
    const float* Wc2    = (const float*)d_in[20];
    const float* bc2    = (const float*)d_in[21];
    float* out = (float*)d_out;
    (void)in_sizes; (void)n_in; (void)out_size;

    float *pGx, *pSeqh, *pQkv, *pAv, *pAo, *pCtx;
    cudaGetSymbolAddress((void**)&pGx, g_Gx);
    cudaGetSymbolAddress((void**)&pSeqh, g_seqh);
    cudaGetSymbolAddress((void**)&pQkv, g_qkv);
    cudaGetSymbolAddress((void**)&pAv, g_av);
    cudaGetSymbolAddress((void**)&pAo, g_attnout);
    cudaGetSymbolAddress((void**)&pCtx, g_ctx);

    cudaFuncSetAttribute(scan_kernel, cudaFuncAttributeMaxDynamicSharedMemorySize, 72 * 1024);
    cudaFuncSetAttribute(flash_kernel, cudaFuncAttributeMaxDynamicSharedMemorySize, 71168);

    // 1) Gx = x @ Wcell[:, :64]^T + b_cell            (M=32768, N=512, K=64)
    gemm_nt_flex<64><<<dim3(8, 512, 1), 256>>>(
        x, 64, 0, 0, W_cell, 192, 1, 0, 0, b_cell, pGx, 512, 0, 0, 32768, 512, 64, 1.f);

    // 2) sequential scan -> seqh
    scan_kernel<<<64, 512, 16 * 512 * sizeof(float2)>>>(W_cell, pGx, pSeqh);

    // 3) qkv = seqh @ Wqkv^T + bqkv                   (M=32768, N=384, K=128)
    gemm_nt_flex<64><<<dim3(6, 512, 1), 256>>>(
        pSeqh, 128, 0, 0, Wqkv, 128, 1, 0, 0, bqkv, pQkv, 384, 0, 0, 32768, 384, 128, 1.f);

    // 4) fused attention v5 (256 threads, 3 CTAs/SM, streamed K/V)
    flash_kernel<<<dim3(4, 256), 256, 71168>>>(pQkv, pAv);

    // 5) attn_out = av @ Wo^T + bo                    (M=32768, N=128, K=128)
    gemm_nt_flex<64><<<dim3(2, 512, 1), 256>>>(
        pAv, 128, 0, 0, Wo, 128, 1, 0, 0, bo, pAo, 128, 0, 0, 32768, 128, 128, 1.f);

    // 6) context = mean_s LN(seqh + attn_out)
    zero_ctx_kernel<<<64, 128>>>(pCtx);
    ln_mean_kernel<<<2048, 128>>>(pSeqh, pAo, ln_g, ln_b, pCtx);

    // 7) heads
    heads_kernel<<<64, 128>>>(pCtx, info, Wa1, ba1, lna_g, lna_b, Wa2, ba2,
                              Wc1, bc1, lnc_g, lnc_b, Wc2, bc2, out);
}

// round 12
// speedup vs baseline: 1.0834x; 1.0834x over previous
#include <cuda_runtime.h>
#include <cuda_fp16.h>
#include <math.h>

typedef unsigned long long ull;

// Problem constants: B=64, S=512, D=64, H=128, HEADS=4, HD=32, I=13, A=3

// -------- scratch (device globals; no allocation) --------
__device__ float g_Gx[32768 * 512];        // x-part of gates + b_cell
__device__ float g_seqh[32768 * 128];      // (b,s,h)
__device__ float g_qkv[32768 * 384 + 64];  // (b,s, q|k|v)
__device__ float g_av[32768 * 128];        // (b,s, head*32+d)
__device__ float g_attnout[32768 * 128];
__device__ float g_ctx[64 * 128];          // sum over s of LN rows

// ---- packed f32x2 helpers ----
__device__ __forceinline__ ull pk2(float a, float b) {
    ull r; asm("mov.b64 %0,{%1,%2};" : "=l"(r) : "f"(a), "f"(b)); return r;
}
__device__ __forceinline__ ull fma2(ull a, ull b, ull c) {
    ull d; asm("fma.rn.f32x2 %0,%1,%2,%3;" : "=l"(d) : "l"(a), "l"(b), "l"(c)); return d;
}
__device__ __forceinline__ ull mul2(ull a, ull b) {
    ull d; asm("mul.rn.f32x2 %0,%1,%2;" : "=l"(d) : "l"(a), "l"(b)); return d;
}
__device__ __forceinline__ float2 up2(ull v) {
    float2 f; asm("mov.b64 {%0,%1},%2;" : "=f"(f.x), "=f"(f.y) : "l"(v)); return f;
}

// ============================================================
// Generic batched NT GEMM (R10 version: 64xBN tile, 4x4 thread
// tile, TK=16, register double-buffer prefetch of next k-tile).
// C[m,n] = alpha*sum_k A[m,k]*B[n,k] + bias[n]
// ============================================================
template <int BN>
__global__ void gemm_nt_flex(
    const float* __restrict__ A, int Am, long long zA1, int zA2,
    const float* __restrict__ B, int Bn, int Bk, long long zB1, int zB2,
    const float* __restrict__ bias,
    float* __restrict__ C, int Cld, long long zC1, int zC2,
    int M, int N, int K, float alpha)
{
    constexpr int TM = 64, TK = 16;
    constexpr int TX = BN / 4;
    constexpr int TPB = TX * 16;
    constexpr int NA = TM * TK / TPB;     // 4 for BN=64
    constexpr int NB = BN * TK / TPB;     // 4
    __shared__ float As[TK][TM + 4];
    __shared__ float Bs[TK][BN + 4];

    int z = blockIdx.z;
    const float* Ab = A + (long long)(z >> 2) * zA1 + (long long)(z & 3) * zA2;
    const float* Bb = B + (long long)(z >> 2) * zB1 + (long long)(z & 3) * zB2;
    float* Cb = C + (long long)(z >> 2) * zC1 + (long long)(z & 3) * zC2;

    int tid = threadIdx.x;
    int tx = tid % TX, ty = tid / TX;
    int m0 = blockIdx.y * TM, n0 = blockIdx.x * BN;

    float aR[NA], bR[NB];

    // prefetch k-tile 0
#pragma unroll
    for (int j = 0; j < NA; j++) {
        int i = tid + j * TPB; int m = i >> 4, k = i & 15;
        aR[j] = Ab[(long long)(m0 + m) * Am + k];
    }
    if (Bk == 1) {
#pragma unroll
        for (int j = 0; j < NB; j++) {
            int i = tid + j * TPB; int n = i >> 4, k = i & 15;
            bR[j] = (n0 + n < N) ? Bb[(long long)(n0 + n) * Bn + k] : 0.f;
        }
    } else {
#pragma unroll
        for (int j = 0; j < NB; j++) {
            int i = tid + j * TPB; int n = i % BN, k = i / BN;
            bR[j] = (n0 + n < N) ? Bb[(long long)(n0 + n) * Bn + (long long)k * Bk] : 0.f;
        }
    }

    ull acc2[4][2] = {};
    for (int k0 = 0; k0 < K; k0 += TK) {
        // store current fragments to smem
#pragma unroll
        for (int j = 0; j < NA; j++) {
            int i = tid + j * TPB; int m = i >> 4, k = i & 15;
            As[k][m] = aR[j];
        }
        if (Bk == 1) {
#pragma unroll
            for (int j = 0; j < NB; j++) {
                int i = tid + j * TPB; int n = i >> 4, k = i & 15;
                Bs[k][n] = bR[j];
            }
        } else {
#pragma unroll
            for (int j = 0; j < NB; j++) {
                int i = tid + j * TPB; int n = i % BN, k = i / BN;
                Bs[k][n] = bR[j];
            }
        }
        __syncthreads();

        // prefetch next k-tile (latency hidden by compute below)
        int k1 = k0 + TK;
        if (k1 < K) {
#pragma unroll
            for (int j = 0; j < NA; j++) {
                int i = tid + j * TPB; int m = i >> 4, k = i & 15;
                aR[j] = Ab[(long long)(m0 + m) * Am + k1 + k];
            }
            if (Bk == 1) {
#pragma unroll
                for (int j = 0; j < NB; j++) {
                    int i = tid + j * TPB; int n = i >> 4, k = i & 15;
                    bR[j] = (n0 + n < N) ? Bb[(long long)(n0 + n) * Bn + k1 + k] : 0.f;
                }
            } else {
#pragma unroll
                for (int j = 0; j < NB; j++) {
                    int i = tid + j * TPB; int n = i % BN, k = i / BN;
                    bR[j] = (n0 + n < N) ? Bb[(long long)(n0 + n) * Bn + (long long)(k1 + k) * Bk] : 0.f;
                }
            }
        }

#pragma unroll
        for (int kk = 0; kk < TK; kk++) {
            float4 a4 = *(const float4*)&As[kk][ty * 4];
            float4 b4 = *(const float4*)&Bs[kk][tx * 4];
            ull bp0 = pk2(b4.x, b4.y), bp1 = pk2(b4.z, b4.w);
            float a[4] = {a4.x, a4.y, a4.z, a4.w};
#pragma unroll
            for (int i = 0; i < 4; i++) {
                ull aa = pk2(a[i], a[i]);
                acc2[i][0] = fma2(aa, bp0, acc2[i][0]);
                acc2[i][1] = fma2(aa, bp1, acc2[i][1]);
            }
        }
        __syncthreads();
    }
#pragma unroll
    for (int i = 0; i < 4; i++) {
        long long m = m0 + ty * 4 + i;
#pragma unroll
        for (int jp = 0; jp < 2; jp++) {
            float2 f = up2(acc2[i][jp]);
            int n = n0 + tx * 4 + 2 * jp;
            if (n < N)     Cb[m * Cld + n]     = alpha * f.x + (bias ? bias[n] : 0.f);
            if (n + 1 < N) Cb[m * Cld + n + 1] = alpha * f.y + (bias ? bias[n + 1] : 0.f);
        }
    }
}

// ============================================================
// Sequential sLSTM scan: 96 weights in regs (f32x2 pairs), 32 in smem.
// Fast-math nonlinear tail (MUFU-based exp/tanh/div).
// ============================================================
__global__ void __launch_bounds__(512, 1)
scan_kernel(const float* __restrict__ Wcell, const float* __restrict__ Gx,
            float* __restrict__ seqh)
{
    extern __shared__ float2 ws2[];  // [16][512]
    __shared__ float h_s[128], c_s[128], n_s[128], gates_s[512];
    int tid = threadIdx.x, b = blockIdx.x;

    ull wr2[48];
    {
        const float4* wrow = (const float4*)(Wcell + tid * 192 + 64);
#pragma unroll
        for (int c = 0; c < 24; c++) {
            float4 w = wrow[c];
            wr2[2 * c] = pk2(w.x, w.y);
            wr2[2 * c + 1] = pk2(w.z, w.w);
        }
    }
#pragma unroll
    for (int p = 0; p < 16; p++)
        ws2[p * 512 + tid] = make_float2(Wcell[tid * 192 + 160 + 2 * p],
                                         Wcell[tid * 192 + 160 + 2 * p + 1]);
    if (tid < 128) { h_s[tid] = 0.f; c_s[tid] = 0.f; n_s[tid] = 1.f; }
    __syncthreads();

    long long gbase = (long long)b * 512 * 512 + tid;
    long long hbase = (long long)b * 512 * 128;
    float gx = Gx[gbase];

    for (int t = 0; t < 512; t++) {
        float gx_next = (t < 511) ? Gx[gbase + (long long)(t + 1) * 512] : 0.f;
        ull a0 = pk2(gx, 0.f), a1 = pk2(0.f, 0.f);
#pragma unroll
        for (int c = 0; c < 24; c++) {
            float4 h4 = *(const float4*)&h_s[c * 4];
            a0 = fma2(wr2[2 * c],     pk2(h4.x, h4.y), a0);
            a1 = fma2(wr2[2 * c + 1], pk2(h4.z, h4.w), a1);
        }
#pragma unroll
        for (int c = 0; c < 8; c++) {
            float4 h4 = *(const float4*)&h_s[96 + c * 4];
            ull wA = *(const ull*)&ws2[(2 * c) * 512 + tid];
            ull wB = *(const ull*)&ws2[(2 * c + 1) * 512 + tid];
            a0 = fma2(wA, pk2(h4.x, h4.y), a0);
            a1 = fma2(wB, pk2(h4.z, h4.w), a1);
        }
        float2 f0 = up2(a0), f1 = up2(a1);
        gates_s[tid] = (f0.x + f0.y) + (f1.x + f1.y);
        __syncthreads();
        if (tid < 128) {
            float gi = gates_s[tid], gf = gates_s[tid + 128];
            float go = gates_s[tid + 256], gz = gates_s[tid + 384];
            float ii = __expf(fminf(fmaxf(gi, -5.f), 5.f));
            float ff = __expf(fminf(fmaxf(gf, -5.f), 5.f));
            float cc = fmaf(ff, c_s[tid], ii * __tanhf(gz));
            cc = fminf(fmaxf(cc, -1e6f), 1e6f);
            float nn = fminf(fmaxf(fmaf(ff, n_s[tid], ii), 1e-6f), 1e6f);
            float sig = __frcp_rn(1.f + __expf(-go));
            float hh = __fdividef(cc, nn) * sig;
            if (!isfinite(hh)) hh = 0.f;
            c_s[tid] = cc; n_s[tid] = nn; h_s[tid] = hh;
            seqh[hbase + (long long)t * 128 + tid] = hh;
        }
        __syncthreads();
        gx = gx_next;
    }
}

// ============================================================
// Fused flash attention v5 (R8/R10 version): 256 threads, 3 CTAs/SM.
// K/V streamed from gmem (L2) in 64-k chunks; Q + P + stats in smem.
// ============================================================
__global__ void __launch_bounds__(256, 3)
flash_kernel(const float* __restrict__ qkv, float* __restrict__ av)
{
    extern __shared__ float sm[];
    float* Qs   = sm;             // [32][132]  4224 (q transposed, pre-scaled)
    float* Ks   = sm + 4224;      // [32][68]   2176 (k chunk transposed)
    float* Vs   = sm + 6400;      // [64][36]   2304 (v chunk row-major)
    float* Ps   = sm + 8704;      // [128][68]  8704
    float* rowM = sm + 17408;     // [128]
    float* rowL = sm + 17536;     // [128]
    float* rowS = sm + 17664;     // [128]  (total 17792 floats = 71168 B)

    int tid = threadIdx.x;
    int qt = blockIdx.x, bh = blockIdx.y;
    int b = bh >> 2, h = bh & 3;
    long long base = (long long)b * 512 * 384 + h * 32;
    int q0 = qt * 128;
    const float alpha = 0.17677669529663687f;

    // -------- stage Q (scaled, transposed) --------
    for (int idx = tid; idx < 128 * 8; idx += 256) {
        int s = idx >> 3, dg = idx & 7;
        float4 v = *(const float4*)&qkv[base + (long long)(q0 + s) * 384 + dg * 4];
        Qs[(dg * 4 + 0) * 132 + s] = v.x * alpha;
        Qs[(dg * 4 + 1) * 132 + s] = v.y * alpha;
        Qs[(dg * 4 + 2) * 132 + s] = v.z * alpha;
        Qs[(dg * 4 + 3) * 132 + s] = v.w * alpha;
    }
    if (tid < 128) { rowM[tid] = -1e30f; rowL[tid] = 0.f; }

    // QK mapping
    int w = tid >> 5, l = tid & 31;
    int lq = l >> 4, lk = l & 15;        // lq 0..1, lk 0..15
    int qrow0 = w * 16 + lq * 8;         // 8 consecutive q
    int kcol0 = lk * 4;                  // 4 consecutive k within chunk
    // PV mapping
    int qg = tid >> 3;                   // q rows {qg, qg+32, qg+64, qg+96}
    int dg = tid & 7;                    // d = 4*dg
    ull out[4][2];
#pragma unroll
    for (int i = 0; i < 4; i++) { out[i][0] = 0ULL; out[i][1] = 0ULL; }

    for (int kt = 0; kt < 8; kt++) {
        int kbase = kt * 64;
        // ---- stage K (transposed) and V (row-major) chunk from gmem/L2 ----
        for (int idx = tid; idx < 64 * 8; idx += 256) {
            int s = idx >> 3, dgi = idx & 7;
            long long grow = base + (long long)(kbase + s) * 384 + dgi * 4;
            float4 kv = *(const float4*)&qkv[grow + 128];
            Ks[(dgi * 4 + 0) * 68 + s] = kv.x;
            Ks[(dgi * 4 + 1) * 68 + s] = kv.y;
            Ks[(dgi * 4 + 2) * 68 + s] = kv.z;
            Ks[(dgi * 4 + 3) * 68 + s] = kv.w;
            float4 vv = *(const float4*)&qkv[grow + 256];
            *(float4*)&Vs[s * 36 + dgi * 4] = vv;
        }
        __syncthreads();

        // ---- QK: acc[8q][2 pairs] ----
        ull acc[8][2];
#pragma unroll
        for (int qi = 0; qi < 8; qi++) { acc[qi][0] = 0ULL; acc[qi][1] = 0ULL; }

#pragma unroll 2
        for (int d = 0; d < 32; d++) {
            float4 kf = *(const float4*)&Ks[d * 68 + kcol0];
            ull kp0 = pk2(kf.x, kf.y), kp1 = pk2(kf.z, kf.w);
            float4 qa = *(const float4*)&Qs[d * 132 + qrow0];
            float4 qb = *(const float4*)&Qs[d * 132 + qrow0 + 4];
            float qv[8] = {qa.x, qa.y, qa.z, qa.w, qb.x, qb.y, qb.z, qb.w};
#pragma unroll
            for (int qi = 0; qi < 8; qi++) {
                ull qq = pk2(qv[qi], qv[qi]);
                acc[qi][0] = fma2(qq, kp0, acc[qi][0]);
                acc[qi][1] = fma2(qq, kp1, acc[qi][1]);
            }
        }
        // ---- online softmax: each row fully inside this warp (16 lk lanes) ----
#pragma unroll
        for (int qi = 0; qi < 8; qi++) {
            float2 fa = up2(acc[qi][0]), fb = up2(acc[qi][1]);
            float p0 = fa.x, p1 = fa.y, p2 = fb.x, p3 = fb.y;
            int q = qrow0 + qi;
            float m_old = rowM[q];
            float tmax = fmaxf(fmaxf(p0, p1), fmaxf(p2, p3));
#pragma unroll
            for (int off = 1; off < 16; off <<= 1)
                tmax = fmaxf(tmax, __shfl_xor_sync(0xffffffffu, tmax, off));
            float mnew = fmaxf(m_old, tmax);
            p0 = __expf(p0 - mnew); p1 = __expf(p1 - mnew);
            p2 = __expf(p2 - mnew); p3 = __expf(p3 - mnew);
            float tsum = (p0 + p1) + (p2 + p3);
#pragma unroll
            for (int off = 1; off < 16; off <<= 1)
                tsum += __shfl_xor_sync(0xffffffffu, tsum, off);
            if (lk == 0) {
                float sc = __expf(m_old - mnew);
                rowS[q] = sc; rowM[q] = mnew;
                rowL[q] = rowL[q] * sc + tsum;
            }
            *(float4*)&Ps[q * 68 + kcol0] = make_float4(p0, p1, p2, p3);
        }
        __syncthreads();

        // ---- PV: thread = 4q (strided 32) x 4d ----
#pragma unroll
        for (int i = 0; i < 4; i++) {
            float sc = rowS[qg + 32 * i];
            ull s2 = pk2(sc, sc);
            out[i][0] = mul2(s2, out[i][0]);
            out[i][1] = mul2(s2, out[i][1]);
        }
#pragma unroll 4
        for (int kl = 0; kl < 64; kl += 2) {
            const float* vr = &Vs[kl * 36 + dg * 4];
            float4 v0 = *(const float4*)&vr[0];
            float4 v1 = *(const float4*)&vr[36];
            ull v0a = pk2(v0.x, v0.y), v0b = pk2(v0.z, v0.w);
            ull v1a = pk2(v1.x, v1.y), v1b = pk2(v1.z, v1.w);
#pragma unroll
            for (int i = 0; i < 4; i++) {
                float2 pf = up2(*(const ull*)&Ps[(qg + 32 * i) * 68 + kl]);
                ull pd0 = pk2(pf.x, pf.x), pd1 = pk2(pf.y, pf.y);
                out[i][0] = fma2(pd0, v0a, out[i][0]);
                out[i][1] = fma2(pd0, v0b, out[i][1]);
                out[i][0] = fma2(pd1, v1a, out[i][0]);
                out[i][1] = fma2(pd1, v1b, out[i][1]);
            }
        }
        __syncthreads();
    }
    // ---- finalize ----
#pragma unroll
    for (int i = 0; i < 4; i++) {
        int q = qg + 32 * i;
        float inv = 1.f / rowL[q];
        ull iv = pk2(inv, inv);
        long long orow = (long long)(b * 512 + q0 + q) * 128 + h * 32 + dg * 4;
        *(ull*)&av[orow] = mul2(iv, out[i][0]);
        *(ull*)&av[orow + 2] = mul2(iv, out[i][1]);
    }
}

// ============================================================
// Reductions (128-thread blocks)
// ============================================================
__device__ __forceinline__ float2 blockReduce2(float a, float b, float2* sh)
{
#pragma unroll
    for (int o = 16; o; o >>= 1) {
        a += __shfl_xor_sync(0xffffffffu, a, o);
        b += __shfl_xor_sync(0xffffffffu, b, o);
    }
    int w = threadIdx.x >> 5;
    if ((threadIdx.x & 31) == 0) sh[w] = make_float2(a, b);
    __syncthreads();
    float2 r;
    r.x = sh[0].x + sh[1].x + sh[2].x + sh[3].x;
    r.y = sh[0].y + sh[1].y + sh[2].y + sh[3].y;
    __syncthreads();
    return r;
}

__global__ void zero_ctx_kernel(float* ctx) { ctx[blockIdx.x * 128 + threadIdx.x] = 0.f; }

__global__ void ln_mean_kernel(const float* __restrict__ seqh, const float* __restrict__ ao,
                               const float* __restrict__ g, const float* __restrict__ bln,
                               float* __restrict__ ctx)
{
    __shared__ float2 sh[4];
    int b = blockIdx.x >> 5, chunk = blockIdx.x & 31;
    int tid = threadIdx.x;
    float acc = 0.f;
    for (int r = 0; r < 16; r++) {
        long long row = ((long long)b * 512 + chunk * 16 + r) * 128;
        float y = seqh[row + tid] + ao[row + tid];
        float2 ss = blockReduce2(y, y * y, sh);
        float mean = ss.x * (1.f / 128.f);
        float var = ss.y * (1.f / 128.f) - mean * mean;
        acc += g[tid] * (y - mean) * rsqrtf(var + 1e-5f) + bln[tid];
    }
    atomicAdd(&ctx[b * 128 + tid], acc);
}

__global__ void heads_kernel(const float* __restrict__ ctx, const float* __restrict__ info,
    const float* __restrict__ Wa1, const float* __restrict__ ba1,
    const float* __restrict__ lna_g, const float* __restrict__ lna_b,
    const float* __restrict__ Wa2, const float* __restrict__ ba2,
    const float* __restrict__ Wc1, const float* __restrict__ bc1,
    const float* __restrict__ lnc_g, const float* __restrict__ lnc_b,
    const float* __restrict__ Wc2, const float* __restrict__ bc2,
    float* __restrict__ out)
{
    __shared__ float comb[144];
    __shared__ float ra[128], rc[128];
    __shared__ float logit[3];
    __shared__ float2 sh[4];
    int b = blockIdx.x, tid = threadIdx.x;
    comb[tid] = ctx[b * 128 + tid] * (1.f / 512.f);
    if (tid < 16) comb[128 + tid] = (tid < 13) ? info[b * 13 + tid] : 0.f;
    __syncthreads();

    float sa = ba1[tid], sc = bc1[tid];
    for (int k = 0; k < 141; k++) {
        sa = fmaf(Wa1[tid * 141 + k], comb[k], sa);
        sc = fmaf(Wc1[tid * 141 + k], comb[k], sc);
    }
    float2 r2 = blockReduce2(sa, sa * sa, sh);
    float ma = r2.x * (1.f / 128.f), va = r2.y * (1.f / 128.f) - ma * ma;
    ra[tid] = fmaxf(lna_g[tid] * (sa - ma) * rsqrtf(va + 1e-5f) + lna_b[tid], 0.f);
    r2 = blockReduce2(sc, sc * sc, sh);
    float mc = r2.x * (1.f / 128.f), vc = r2.y * (1.f / 128.f) - mc * mc;
    rc[tid] = fmaxf(lnc_g[tid] * (sc - mc) * rsqrtf(vc + 1e-5f) + lnc_b[tid], 0.f);
    __syncthreads();

    if (tid < 3) {
        float l = ba2[tid];
        for (int k = 0; k < 128; k++) l = fmaf(Wa2[tid * 128 + k], ra[k], l);
        logit[tid] = l;
    }
    float2 vv = blockReduce2(rc[tid] * Wc2[tid], 0.f, sh);
    if (tid == 0) out[192 + b] = vv.x + bc2[0];
    __syncthreads();
    if (tid == 0) {
        float m = fmaxf(logit[0], fmaxf(logit[1], logit[2]));
        float e0 = expf(logit[0] - m), e1 = expf(logit[1] - m), e2 = expf(logit[2] - m);
        float inv = 1.f / (e0 + e1 + e2);
        out[b * 3 + 0] = e0 * inv;
        out[b * 3 + 1] = e1 * inv;
        out[b * 3 + 2] = e2 * inv;
    }
}

// ============================================================
extern "C" void kernel_launch(void* const* d_in, const int* in_sizes, int n_in,
                              void* d_out, int out_size)
{
    const float* x      = (const float*)d_in[0];
    const float* info   = (const float*)d_in[1];
    const float* W_cell = (const float*)d_in[2];
    const float* b_cell = (const float*)d_in[3];
    const float* Wqkv   = (const float*)d_in[4];
    const float* bqkv   = (const float*)d_in[5];
    const float* Wo     = (const float*)d_in[6];
    const float* bo     = (const float*)d_in[7];
    const float* ln_g   = (const float*)d_in[8];
    const float* ln_b   = (const float*)d_in[9];
    const float* Wa1    = (const float*)d_in[10];
    const float* ba1    = (const float*)d_in[11];
    const float* lna_g  = (const float*)d_in[12];
    const float* lna_b  = (const float*)d_in[13];
    const float* Wa2    = (const float*)d_in[14];
    const float* ba2    = (const float*)d_in[15];
    const float* Wc1    = (const float*)d_in[16];
    const float* bc1    = (const float*)d_in[17];
    const float* lnc_g  = (const float*)d_in[18];
    const float* lnc_b  = (const float*)d_in[19];
    const float* Wc2    = (const float*)d_in[20];
    const float* bc2    = (const float*)d_in[21];
    float* out = (float*)d_out;
    (void)in_sizes; (void)n_in; (void)out_size;

    float *pGx, *pSeqh, *pQkv, *pAv, *pAo, *pCtx;
    cudaGetSymbolAddress((void**)&pGx, g_Gx);
    cudaGetSymbolAddress((void**)&pSeqh, g_seqh);
    cudaGetSymbolAddress((void**)&pQkv, g_qkv);
    cudaGetSymbolAddress((void**)&pAv, g_av);
    cudaGetSymbolAddress((void**)&pAo, g_attnout);
    cudaGetSymbolAddress((void**)&pCtx, g_ctx);

    cudaFuncSetAttribute(scan_kernel, cudaFuncAttributeMaxDynamicSharedMemorySize, 72 * 1024);
    cudaFuncSetAttribute(flash_kernel, cudaFuncAttributeMaxDynamicSharedMemorySize, 71168);

    // 1) Gx = x @ Wcell[:, :64]^T + b_cell            (M=32768, N=512, K=64)
    gemm_nt_flex<64><<<dim3(8, 512, 1), 256>>>(
        x, 64, 0, 0, W_cell, 192, 1, 0, 0, b_cell, pGx, 512, 0, 0, 32768, 512, 64, 1.f);

    // 2) sequential scan -> seqh
    scan_kernel<<<64, 512, 16 * 512 * sizeof(float2)>>>(W_cell, pGx, pSeqh);

    // 3) qkv = seqh @ Wqkv^T + bqkv                   (M=32768, N=384, K=128)
    gemm_nt_flex<64><<<dim3(6, 512, 1), 256>>>(
        pSeqh, 128, 0, 0, Wqkv, 128, 1, 0, 0, bqkv, pQkv, 384, 0, 0, 32768, 384, 128, 1.f);

    // 4) fused attention v5 (256 threads, 3 CTAs/SM, streamed K/V)
    flash_kernel<<<dim3(4, 256), 256, 71168>>>(pQkv, pAv);

    // 5) attn_out = av @ Wo^T + bo                    (M=32768, N=128, K=128)
    gemm_nt_flex<64><<<dim3(2, 512, 1), 256>>>(
        pAv, 128, 0, 0, Wo, 128, 1, 0, 0, bo, pAo, 128, 0, 0, 32768, 128, 128, 1.f);

    // 6) context = mean_s LN(seqh + attn_out)
    zero_ctx_kernel<<<64, 128>>>(pCtx);
    ln_mean_kernel<<<2048, 128>>>(pSeqh, pAo, ln_g, ln_b, pCtx);

    // 7) heads
    heads_kernel<<<64, 128>>>(pCtx, info, Wa1, ba1, lna_g, lna_b, Wa2, ba2,
                              Wc1, bc1, lnc_g, lnc_b, Wc2, bc2, out);
}

// round 14
// speedup vs baseline: 1.3234x; 1.2215x over previous
#include <cuda_runtime.h>
#include <cuda_fp16.h>
#include <cuda_bf16.h>
#include <stdint.h>
#include <math.h>

typedef unsigned long long ull;

// Problem constants: B=64, S=512, D=64, H=128, HEADS=4, HD=32, I=13, A=3

// -------- scratch (device globals; no allocation) --------
__device__ float g_Gx[32768 * 512];
__device__ float g_seqh[32768 * 128];
__device__ float g_qkv[32768 * 384 + 64];
__device__ float g_av[32768 * 128];
__device__ float g_attnout[32768 * 128];
__device__ float g_ctx[64 * 128];

// ---- packed f32x2 helpers ----
__device__ __forceinline__ ull pk2(float a, float b) {
    ull r; asm("mov.b64 %0,{%1,%2};" : "=l"(r) : "f"(a), "f"(b)); return r;
}
__device__ __forceinline__ ull fma2(ull a, ull b, ull c) {
    ull d; asm("fma.rn.f32x2 %0,%1,%2,%3;" : "=l"(d) : "l"(a), "l"(b), "l"(c)); return d;
}
__device__ __forceinline__ ull mul2(ull a, ull b) {
    ull d; asm("mul.rn.f32x2 %0,%1,%2;" : "=l"(d) : "l"(a), "l"(b)); return d;
}
__device__ __forceinline__ float2 up2(ull v) {
    float2 f; asm("mov.b64 {%0,%1},%2;" : "=f"(f.x), "=f"(f.y) : "l"(v)); return f;
}
__device__ __forceinline__ float ex2f(float x) {
    float y; asm("ex2.approx.ftz.f32 %0,%1;" : "=f"(y) : "f"(x)); return y;
}

// ---- tensor-core helpers (bf16 m16n8k16) ----
__device__ __forceinline__ void ldsm4(uint32_t* r, uint32_t a) {
    asm volatile("ldmatrix.sync.aligned.m8n8.x4.shared.b16 {%0,%1,%2,%3},[%4];"
        : "=r"(r[0]), "=r"(r[1]), "=r"(r[2]), "=r"(r[3]) : "r"(a));
}
__device__ __forceinline__ void ldsm2(uint32_t& b0, uint32_t& b1, uint32_t a) {
    asm volatile("ldmatrix.sync.aligned.m8n8.x2.shared.b16 {%0,%1},[%2];"
        : "=r"(b0), "=r"(b1) : "r"(a));
}
__device__ __forceinline__ void ldsm2t(uint32_t& b0, uint32_t& b1, uint32_t a) {
    asm volatile("ldmatrix.sync.aligned.m8n8.x2.trans.shared.b16 {%0,%1},[%2];"
        : "=r"(b0), "=r"(b1) : "r"(a));
}
__device__ __forceinline__ void mma16816(float* c, const uint32_t* a, uint32_t b0, uint32_t b1) {
    asm volatile("mma.sync.aligned.m16n8k16.row.col.f32.bf16.bf16.f32 "
        "{%0,%1,%2,%3},{%4,%5,%6,%7},{%8,%9},{%0,%1,%2,%3};"
        : "+f"(c[0]), "+f"(c[1]), "+f"(c[2]), "+f"(c[3])
        : "r"(a[0]), "r"(a[1]), "r"(a[2]), "r"(a[3]), "r"(b0), "r"(b1));
}

// ============================================================
// Generic batched NT GEMM (R12 version, unchanged)
// ============================================================
template <int BN>
__global__ void gemm_nt_flex(
    const float* __restrict__ A, int Am, long long zA1, int zA2,
    const float* __restrict__ B, int Bn, int Bk, long long zB1, int zB2,
    const float* __restrict__ bias,
    float* __restrict__ C, int Cld, long long zC1, int zC2,
    int M, int N, int K, float alpha)
{
    constexpr int TM = 64, TK = 16;
    constexpr int TX = BN / 4;
    constexpr int TPB = TX * 16;
    constexpr int NA = TM * TK / TPB;
    constexpr int NB = BN * TK / TPB;
    __shared__ float As[TK][TM + 4];
    __shared__ float Bs[TK][BN + 4];

    int z = blockIdx.z;
    const float* Ab = A + (long long)(z >> 2) * zA1 + (long long)(z & 3) * zA2;
    const float* Bb = B + (long long)(z >> 2) * zB1 + (long long)(z & 3) * zB2;
    float* Cb = C + (long long)(z >> 2) * zC1 + (long long)(z & 3) * zC2;

    int tid = threadIdx.x;
    int tx = tid % TX, ty = tid / TX;
    int m0 = blockIdx.y * TM, n0 = blockIdx.x * BN;

    float aR[NA], bR[NB];

#pragma unroll
    for (int j = 0; j < NA; j++) {
        int i = tid + j * TPB; int m = i >> 4, k = i & 15;
        aR[j] = Ab[(long long)(m0 + m) * Am + k];
    }
    if (Bk == 1) {
#pragma unroll
        for (int j = 0; j < NB; j++) {
            int i = tid + j * TPB; int n = i >> 4, k = i & 15;
            bR[j] = (n0 + n < N) ? Bb[(long long)(n0 + n) * Bn + k] : 0.f;
        }
    } else {
#pragma unroll
        for (int j = 0; j < NB; j++) {
            int i = tid + j * TPB; int n = i % BN, k = i / BN;
            bR[j] = (n0 + n < N) ? Bb[(long long)(n0 + n) * Bn + (long long)k * Bk] : 0.f;
        }
    }

    ull acc2[4][2] = {};
    for (int k0 = 0; k0 < K; k0 += TK) {
#pragma unroll
        for (int j = 0; j < NA; j++) {
            int i = tid + j * TPB; int m = i >> 4, k = i & 15;
            As[k][m] = aR[j];
        }
        if (Bk == 1) {
#pragma unroll
            for (int j = 0; j < NB; j++) {
                int i = tid + j * TPB; int n = i >> 4, k = i & 15;
                Bs[k][n] = bR[j];
            }
        } else {
#pragma unroll
            for (int j = 0; j < NB; j++) {
                int i = tid + j * TPB; int n = i % BN, k = i / BN;
                Bs[k][n] = bR[j];
            }
        }
        __syncthreads();

        int k1 = k0 + TK;
        if (k1 < K) {
#pragma unroll
            for (int j = 0; j < NA; j++) {
                int i = tid + j * TPB; int m = i >> 4, k = i & 15;
                aR[j] = Ab[(long long)(m0 + m) * Am + k1 + k];
            }
            if (Bk == 1) {
#pragma unroll
                for (int j = 0; j < NB; j++) {
                    int i = tid + j * TPB; int n = i >> 4, k = i & 15;
                    bR[j] = (n0 + n < N) ? Bb[(long long)(n0 + n) * Bn + k1 + k] : 0.f;
                }
            } else {
#pragma unroll
                for (int j = 0; j < NB; j++) {
                    int i = tid + j * TPB; int n = i % BN, k = i / BN;
                    bR[j] = (n0 + n < N) ? Bb[(long long)(n0 + n) * Bn + (long long)(k1 + k) * Bk] : 0.f;
                }
            }
        }

#pragma unroll
        for (int kk = 0; kk < TK; kk++) {
            float4 a4 = *(const float4*)&As[kk][ty * 4];
            float4 b4 = *(const float4*)&Bs[kk][tx * 4];
            ull bp0 = pk2(b4.x, b4.y), bp1 = pk2(b4.z, b4.w);
            float a[4] = {a4.x, a4.y, a4.z, a4.w};
#pragma unroll
            for (int i = 0; i < 4; i++) {
                ull aa = pk2(a[i], a[i]);
                acc2[i][0] = fma2(aa, bp0, acc2[i][0]);
                acc2[i][1] = fma2(aa, bp1, acc2[i][1]);
            }
        }
        __syncthreads();
    }
#pragma unroll
    for (int i = 0; i < 4; i++) {
        long long m = m0 + ty * 4 + i;
#pragma unroll
        for (int jp = 0; jp < 2; jp++) {
            float2 f = up2(acc2[i][jp]);
            int n = n0 + tx * 4 + 2 * jp;
            if (n < N)     Cb[m * Cld + n]     = alpha * f.x + (bias ? bias[n] : 0.f);
            if (n + 1 < N) Cb[m * Cld + n + 1] = alpha * f.y + (bias ? bias[n + 1] : 0.f);
        }
    }
}

// ============================================================
// Sequential sLSTM scan (R12 version, unchanged)
// ============================================================
__global__ void __launch_bounds__(512, 1)
scan_kernel(const float* __restrict__ Wcell, const float* __restrict__ Gx,
            float* __restrict__ seqh)
{
    extern __shared__ float2 ws2[];
    __shared__ float h_s[128], c_s[128], n_s[128], gates_s[512];
    int tid = threadIdx.x, b = blockIdx.x;

    ull wr2[48];
    {
        const float4* wrow = (const float4*)(Wcell + tid * 192 + 64);
#pragma unroll
        for (int c = 0; c < 24; c++) {
            float4 w = wrow[c];
            wr2[2 * c] = pk2(w.x, w.y);
            wr2[2 * c + 1] = pk2(w.z, w.w);
        }
    }
#pragma unroll
    for (int p = 0; p < 16; p++)
        ws2[p * 512 + tid] = make_float2(Wcell[tid * 192 + 160 + 2 * p],
                                         Wcell[tid * 192 + 160 + 2 * p + 1]);
    if (tid < 128) { h_s[tid] = 0.f; c_s[tid] = 0.f; n_s[tid] = 1.f; }
    __syncthreads();

    long long gbase = (long long)b * 512 * 512 + tid;
    long long hbase = (long long)b * 512 * 128;
    float gx = Gx[gbase];

    for (int t = 0; t < 512; t++) {
        float gx_next = (t < 511) ? Gx[gbase + (long long)(t + 1) * 512] : 0.f;
        ull a0 = pk2(gx, 0.f), a1 = pk2(0.f, 0.f);
#pragma unroll
        for (int c = 0; c < 24; c++) {
            float4 h4 = *(const float4*)&h_s[c * 4];
            a0 = fma2(wr2[2 * c],     pk2(h4.x, h4.y), a0);
            a1 = fma2(wr2[2 * c + 1], pk2(h4.z, h4.w), a1);
        }
#pragma unroll
        for (int c = 0; c < 8; c++) {
            float4 h4 = *(const float4*)&h_s[96 + c * 4];
            ull wA = *(const ull*)&ws2[(2 * c) * 512 + tid];
            ull wB = *(const ull*)&ws2[(2 * c + 1) * 512 + tid];
            a0 = fma2(wA, pk2(h4.x, h4.y), a0);
            a1 = fma2(wB, pk2(h4.z, h4.w), a1);
        }
        float2 f0 = up2(a0), f1 = up2(a1);
        gates_s[tid] = (f0.x + f0.y) + (f1.x + f1.y);
        __syncthreads();
        if (tid < 128) {
            float gi = gates_s[tid], gf = gates_s[tid + 128];
            float go = gates_s[tid + 256], gz = gates_s[tid + 384];
            float ii = __expf(fminf(fmaxf(gi, -5.f), 5.f));
            float ff = __expf(fminf(fmaxf(gf, -5.f), 5.f));
            float cc = fmaf(ff, c_s[tid], ii * __tanhf(gz));
            cc = fminf(fmaxf(cc, -1e6f), 1e6f);
            float nn = fminf(fmaxf(fmaf(ff, n_s[tid], ii), 1e-6f), 1e6f);
            float sig = __frcp_rn(1.f + __expf(-go));
            float hh = __fdividef(cc, nn) * sig;
            if (!isfinite(hh)) hh = 0.f;
            c_s[tid] = cc; n_s[tid] = nn; h_s[tid] = hh;
            seqh[hbase + (long long)t * 128 + tid] = hh;
        }
        __syncthreads();
        gx = gx_next;
    }
}

// ============================================================
// Fused flash attention v6: bf16 mma.sync.m16n8k16, 256 thr, 3 CTA/SM.
// Warp w owns q rows [16w,16w+16). K/V streamed in 64-k chunks.
// Softmax in exp2 domain on C fragments; P -> bf16 smem -> A frag.
// ============================================================
__global__ void __launch_bounds__(256, 3)
flash_kernel(const float* __restrict__ qkv, float* __restrict__ av)
{
    extern __shared__ char smraw[];
    __nv_bfloat16* Qs = (__nv_bfloat16*)(smraw);          // [128][40]
    __nv_bfloat16* Ks = (__nv_bfloat16*)(smraw + 10240);  // [64][40]
    __nv_bfloat16* Vs = (__nv_bfloat16*)(smraw + 15360);  // [64][40]
    __nv_bfloat16* Ps = (__nv_bfloat16*)(smraw + 20480);  // [128][72]
    float* rowM = (float*)(smraw + 38912);
    float* rowL = (float*)(smraw + 39424);
    float* rowS = (float*)(smraw + 39936);                // end 40448

    int tid = threadIdx.x;
    int qt = blockIdx.x;
    int bh = blockIdx.y;
    int b = bh >> 2;
    int h = bh & 3;
    long long base = (long long)b * 512 * 384 + h * 32;
    int q0 = qt * 128;
    const float alpha = 0.25501398f;  // (1/sqrt(32)) * log2(e)

    for (int idx = tid; idx < 1024; idx += 256) {
        int s = idx >> 3;
        int dg = idx & 7;
        float4 v = *(const float4*)&qkv[base + (long long)(q0 + s) * 384 + dg * 4];
        __nv_bfloat162 p0 = __floats2bfloat162_rn(v.x * alpha, v.y * alpha);
        __nv_bfloat162 p1 = __floats2bfloat162_rn(v.z * alpha, v.w * alpha);
        uint2 pk; pk.x = *(uint32_t*)&p0; pk.y = *(uint32_t*)&p1;
        *(uint2*)&Qs[s * 40 + dg * 4] = pk;
    }
    if (tid < 128) { rowM[tid] = -1e30f; rowL[tid] = 0.f; }
    __syncthreads();

    int w = tid >> 5;
    int lane = tid & 31;
    uint32_t sb = (uint32_t)__cvta_generic_to_shared(smraw);

    uint32_t aq0[4];
    uint32_t aq1[4];
    {
        uint32_t qaddr = sb + ((16 * w + (lane & 15)) * 40 + (lane >> 4) * 8) * 2;
        ldsm4(aq0, qaddr);
        ldsm4(aq1, qaddr + 32);
    }

    int qA = 16 * w + (lane >> 2);
    int qB = qA + 8;
    float of[4][4];
#pragma unroll
    for (int i = 0; i < 4; i++) {
        of[i][0] = 0.f; of[i][1] = 0.f; of[i][2] = 0.f; of[i][3] = 0.f;
    }

    for (int kt = 0; kt < 8; kt++) {
        int kbase = kt * 64;
        for (int idx = tid; idx < 512; idx += 256) {
            int s = idx >> 3;
            int dg = idx & 7;
            long long grow = base + (long long)(kbase + s) * 384 + dg * 4;
            float4 kv = *(const float4*)&qkv[grow + 128];
            float4 vv = *(const float4*)&qkv[grow + 256];
            __nv_bfloat162 k0 = __floats2bfloat162_rn(kv.x, kv.y);
            __nv_bfloat162 k1 = __floats2bfloat162_rn(kv.z, kv.w);
            uint2 kk; kk.x = *(uint32_t*)&k0; kk.y = *(uint32_t*)&k1;
            *(uint2*)&Ks[s * 40 + dg * 4] = kk;
            __nv_bfloat162 v0 = __floats2bfloat162_rn(vv.x, vv.y);
            __nv_bfloat162 v1 = __floats2bfloat162_rn(vv.z, vv.w);
            uint2 vp; vp.x = *(uint32_t*)&v0; vp.y = *(uint32_t*)&v1;
            *(uint2*)&Vs[s * 40 + dg * 4] = vp;
        }
        __syncthreads();

        float cf[8][4];
#pragma unroll
        for (int nt = 0; nt < 8; nt++) {
            cf[nt][0] = 0.f; cf[nt][1] = 0.f; cf[nt][2] = 0.f; cf[nt][3] = 0.f;
        }
        uint32_t kaddr0 = sb + 10240 + ((lane & 7) * 40 + ((lane >> 3) & 1) * 8) * 2;
#pragma unroll
        for (int nt = 0; nt < 8; nt++) {
            uint32_t addr = kaddr0 + nt * 640;   // 8 rows * 40 elems * 2 B
            uint32_t b0, b1;
            ldsm2(b0, b1, addr);
            mma16816(cf[nt], aq0, b0, b1);
            ldsm2(b0, b1, addr + 32);
            mma16816(cf[nt], aq1, b0, b1);
        }

        float moA = rowM[qA];
        float moB = rowM[qB];
        float mxA = cf[0][0];
        float mxB = cf[0][2];
#pragma unroll
        for (int nt = 0; nt < 8; nt++) {
            mxA = fmaxf(mxA, fmaxf(cf[nt][0], cf[nt][1]));
            mxB = fmaxf(mxB, fmaxf(cf[nt][2], cf[nt][3]));
        }
        mxA = fmaxf(mxA, __shfl_xor_sync(0xffffffffu, mxA, 1));
        mxA = fmaxf(mxA, __shfl_xor_sync(0xffffffffu, mxA, 2));
        mxB = fmaxf(mxB, __shfl_xor_sync(0xffffffffu, mxB, 1));
        mxB = fmaxf(mxB, __shfl_xor_sync(0xffffffffu, mxB, 2));
        float mnA = fmaxf(moA, mxA);
        float mnB = fmaxf(moB, mxB);
        float sumA = 0.f, sumB = 0.f;
        int colo = (lane & 3) * 2;
#pragma unroll
        for (int nt = 0; nt < 8; nt++) {
            float e0 = ex2f(cf[nt][0] - mnA);
            float e1 = ex2f(cf[nt][1] - mnA);
            float e2 = ex2f(cf[nt][2] - mnB);
            float e3 = ex2f(cf[nt][3] - mnB);
            sumA += e0 + e1;
            sumB += e2 + e3;
            __nv_bfloat162 pa = __floats2bfloat162_rn(e0, e1);
            __nv_bfloat162 pb = __floats2bfloat162_rn(e2, e3);
            *(uint32_t*)&Ps[qA * 72 + nt * 8 + colo] = *(uint32_t*)&pa;
            *(uint32_t*)&Ps[qB * 72 + nt * 8 + colo] = *(uint32_t*)&pb;
        }
        sumA += __shfl_xor_sync(0xffffffffu, sumA, 1);
        sumA += __shfl_xor_sync(0xffffffffu, sumA, 2);
        sumB += __shfl_xor_sync(0xffffffffu, sumB, 1);
        sumB += __shfl_xor_sync(0xffffffffu, sumB, 2);
        if ((lane & 3) == 0) {
            float scA = ex2f(moA - mnA);
            float scB = ex2f(moB - mnB);
            rowS[qA] = scA; rowM[qA] = mnA; rowL[qA] = rowL[qA] * scA + sumA;
            rowS[qB] = scB; rowM[qB] = mnB; rowL[qB] = rowL[qB] * scB + sumB;
        }
        __syncwarp();

        {
            float scA = rowS[qA];
            float scB = rowS[qB];
#pragma unroll
            for (int i = 0; i < 4; i++) {
                of[i][0] *= scA; of[i][1] *= scA;
                of[i][2] *= scB; of[i][3] *= scB;
            }
        }
        uint32_t paddr0 = sb + 20480 + ((16 * w + (lane & 15)) * 72 + (lane >> 4) * 8) * 2;
        uint32_t vaddr0 = sb + 15360 + ((lane & 15) * 40) * 2;
#pragma unroll
        for (int ks = 0; ks < 4; ks++) {
            uint32_t ap[4];
            ldsm4(ap, paddr0 + ks * 32);
#pragma unroll
            for (int nt2 = 0; nt2 < 4; nt2++) {
                uint32_t b0, b1;
                ldsm2t(b0, b1, vaddr0 + ks * 1280 + nt2 * 16);  // 16 rows*80B per ks
                mma16816(of[nt2], ap, b0, b1);
            }
        }
        __syncthreads();
    }

    {
        float iA = 1.f / rowL[qA];
        float iB = 1.f / rowL[qB];
        long long orA = (long long)(b * 512 + q0 + qA) * 128 + h * 32 + (lane & 3) * 2;
        long long orB = orA + 8LL * 128;
#pragma unroll
        for (int nt2 = 0; nt2 < 4; nt2++) {
            float2 ra; ra.x = of[nt2][0] * iA; ra.y = of[nt2][1] * iA;
            float2 rb; rb.x = of[nt2][2] * iB; rb.y = of[nt2][3] * iB;
            *(float2*)&av[orA + nt2 * 8] = ra;
            *(float2*)&av[orB + nt2 * 8] = rb;
        }
    }
}

// ============================================================
// Reductions (128-thread blocks)
// ============================================================
__device__ __forceinline__ float2 blockReduce2(float a, float b, float2* sh)
{
#pragma unroll
    for (int o = 16; o; o >>= 1) {
        a += __shfl_xor_sync(0xffffffffu, a, o);
        b += __shfl_xor_sync(0xffffffffu, b, o);
    }
    int w = threadIdx.x >> 5;
    if ((threadIdx.x & 31) == 0) sh[w] = make_float2(a, b);
    __syncthreads();
    float2 r;
    r.x = sh[0].x + sh[1].x + sh[2].x + sh[3].x;
    r.y = sh[0].y + sh[1].y + sh[2].y + sh[3].y;
    __syncthreads();
    return r;
}

__global__ void zero_ctx_kernel(float* ctx) { ctx[blockIdx.x * 128 + threadIdx.x] = 0.f; }

__global__ void ln_mean_kernel(const float* __restrict__ seqh, const float* __restrict__ ao,
                               const float* __restrict__ g, const float* __restrict__ bln,
                               float* __restrict__ ctx)
{
    __shared__ float2 sh[4];
    int b = blockIdx.x >> 5, chunk = blockIdx.x & 31;
    int tid = threadIdx.x;
    float acc = 0.f;
    for (int r = 0; r < 16; r++) {
        long long row = ((long long)b * 512 + chunk * 16 + r) * 128;
        float y = seqh[row + tid] + ao[row + tid];
        float2 ss = blockReduce2(y, y * y, sh);
        float mean = ss.x * (1.f / 128.f);
        float var = ss.y * (1.f / 128.f) - mean * mean;
        acc += g[tid] * (y - mean) * rsqrtf(var + 1e-5f) + bln[tid];
    }
    atomicAdd(&ctx[b * 128 + tid], acc);
}

__global__ void heads_kernel(const float* __restrict__ ctx, const float* __restrict__ info,
    const float* __restrict__ Wa1, const float* __restrict__ ba1,
    const float* __restrict__ lna_g, const float* __restrict__ lna_b,
    const float* __restrict__ Wa2, const float* __restrict__ ba2,
    const float* __restrict__ Wc1, const float* __restrict__ bc1,
    const float* __restrict__ lnc_g, const float* __restrict__ lnc_b,
    const float* __restrict__ Wc2, const float* __restrict__ bc2,
    float* __restrict__ out)
{
    __shared__ float comb[144];
    __shared__ float ra[128], rc[128];
    __shared__ float logit[3];
    __shared__ float2 sh[4];
    int b = blockIdx.x, tid = threadIdx.x;
    comb[tid] = ctx[b * 128 + tid] * (1.f / 512.f);
    if (tid < 16) comb[128 + tid] = (tid < 13) ? info[b * 13 + tid] : 0.f;
    __syncthreads();

    float sa = ba1[tid], sc = bc1[tid];
    for (int k = 0; k < 141; k++) {
        sa = fmaf(Wa1[tid * 141 + k], comb[k], sa);
        sc = fmaf(Wc1[tid * 141 + k], comb[k], sc);
    }
    float2 r2 = blockReduce2(sa, sa * sa, sh);
    float ma = r2.x * (1.f / 128.f), va = r2.y * (1.f / 128.f) - ma * ma;
    ra[tid] = fmaxf(lna_g[tid] * (sa - ma) * rsqrtf(va + 1e-5f) + lna_b[tid], 0.f);
    r2 = blockReduce2(sc, sc * sc, sh);
    float mc = r2.x * (1.f / 128.f), vc = r2.y * (1.f / 128.f) - mc * mc;
    rc[tid] = fmaxf(lnc_g[tid] * (sc - mc) * rsqrtf(vc + 1e-5f) + lnc_b[tid], 0.f);
    __syncthreads();

    if (tid < 3) {
        float l = ba2[tid];
        for (int k = 0; k < 128; k++) l = fmaf(Wa2[tid * 128 + k], ra[k], l);
        logit[tid] = l;
    }
    float2 vv = blockReduce2(rc[tid] * Wc2[tid], 0.f, sh);
    if (tid == 0) out[192 + b] = vv.x + bc2[0];
    __syncthreads();
    if (tid == 0) {
        float m = fmaxf(logit[0], fmaxf(logit[1], logit[2]));
        float e0 = expf(logit[0] - m), e1 = expf(logit[1] - m), e2 = expf(logit[2] - m);
        float inv = 1.f / (e0 + e1 + e2);
        out[b * 3 + 0] = e0 * inv;
        out[b * 3 + 1] = e1 * inv;
        out[b * 3 + 2] = e2 * inv;
    }
}

// ============================================================
extern "C" void kernel_launch(void* const* d_in, const int* in_sizes, int n_in,
                              void* d_out, int out_size)
{
    const float* x      = (const float*)d_in[0];
    const float* info   = (const float*)d_in[1];
    const float* W_cell = (const float*)d_in[2];
    const float* b_cell = (const float*)d_in[3];
    const float* Wqkv   = (const float*)d_in[4];
    const float* bqkv   = (const float*)d_in[5];
    const float* Wo     = (const float*)d_in[6];
    const float* bo     = (const float*)d_in[7];
    const float* ln_g   = (const float*)d_in[8];
    const float* ln_b   = (const float*)d_in[9];
    const float* Wa1    = (const float*)d_in[10];
    const float* ba1    = (const float*)d_in[11];
    const float* lna_g  = (const float*)d_in[12];
    const float* lna_b  = (const float*)d_in[13];
    const float* Wa2    = (const float*)d_in[14];
    const float* ba2    = (const float*)d_in[15];
    const float* Wc1    = (const float*)d_in[16];
    const float* bc1    = (const float*)d_in[17];
    const float* lnc_g  = (const float*)d_in[18];
    const float* lnc_b  = (const float*)d_in[19];
    const float* Wc2    = (const float*)d_in[20];
    const float* bc2    = (const float*)d_in[21];
    float* out = (float*)d_out;
    (void)in_sizes; (void)n_in; (void)out_size;

    float *pGx, *pSeqh, *pQkv, *pAv, *pAo, *pCtx;
    cudaGetSymbolAddress((void**)&pGx, g_Gx);
    cudaGetSymbolAddress((void**)&pSeqh, g_seqh);
    cudaGetSymbolAddress((void**)&pQkv, g_qkv);
    cudaGetSymbolAddress((void**)&pAv, g_av);
    cudaGetSymbolAddress((void**)&pAo, g_attnout);
    cudaGetSymbolAddress((void**)&pCtx, g_ctx);

    cudaFuncSetAttribute(scan_kernel, cudaFuncAttributeMaxDynamicSharedMemorySize, 72 * 1024);
    cudaFuncSetAttribute(flash_kernel, cudaFuncAttributeMaxDynamicSharedMemorySize, 40448);

    // 1) Gx = x @ Wcell[:, :64]^T + b_cell            (M=32768, N=512, K=64)
    gemm_nt_flex<64><<<dim3(8, 512, 1), 256>>>(
        x, 64, 0, 0, W_cell, 192, 1, 0, 0, b_cell, pGx, 512, 0, 0, 32768, 512, 64, 1.f);

    // 2) sequential scan -> seqh
    scan_kernel<<<64, 512, 16 * 512 * sizeof(float2)>>>(W_cell, pGx, pSeqh);

    // 3) qkv = seqh @ Wqkv^T + bqkv                   (M=32768, N=384, K=128)
    gemm_nt_flex<64><<<dim3(6, 512, 1), 256>>>(
        pSeqh, 128, 0, 0, Wqkv, 128, 1, 0, 0, bqkv, pQkv, 384, 0, 0, 32768, 384, 128, 1.f);

    // 4) fused attention v6 (bf16 tensor cores)
    flash_kernel<<<dim3(4, 256), 256, 40448>>>(pQkv, pAv);

    // 5) attn_out = av @ Wo^T + bo                    (M=32768, N=128, K=128)
    gemm_nt_flex<64><<<dim3(2, 512, 1), 256>>>(
        pAv, 128, 0, 0, Wo, 128, 1, 0, 0, bo, pAo, 128, 0, 0, 32768, 128, 128, 1.f);

    // 6) context = mean_s LN(seqh + attn_out)
    zero_ctx_kernel<<<64, 128>>>(pCtx);
    ln_mean_kernel<<<2048, 128>>>(pSeqh, pAo, ln_g, ln_b, pCtx);

    // 7) heads
    heads_kernel<<<64, 128>>>(pCtx, info, Wa1, ba1, lna_g, lna_b, Wa2, ba2,
                              Wc1, bc1, lnc_g, lnc_b, Wc2, bc2, out);
}

// round 16
// speedup vs baseline: 1.4587x; 1.1023x over previous
#include <cuda_runtime.h>
#include <cuda_fp16.h>
#include <cuda_bf16.h>
#include <stdint.h>
#include <math.h>

typedef unsigned long long ull;

// Problem constants: B=64, S=512, D=64, H=128, HEADS=4, HD=32, I=13, A=3

// -------- scratch (device globals; no allocation) --------
__device__ float g_Gx[32768 * 512];
__device__ float g_seqh[32768 * 128];
__device__ float g_qkv[32768 * 384 + 64];
__device__ float g_av[32768 * 128];
__device__ float g_attnout[32768 * 128];
__device__ float g_ctx[64 * 128];

// ---- packed f32x2 helpers ----
__device__ __forceinline__ ull pk2(float a, float b) {
    ull r; asm("mov.b64 %0,{%1,%2};" : "=l"(r) : "f"(a), "f"(b)); return r;
}
__device__ __forceinline__ ull fma2(ull a, ull b, ull c) {
    ull d; asm("fma.rn.f32x2 %0,%1,%2,%3;" : "=l"(d) : "l"(a), "l"(b), "l"(c)); return d;
}
__device__ __forceinline__ ull mul2(ull a, ull b) {
    ull d; asm("mul.rn.f32x2 %0,%1,%2;" : "=l"(d) : "l"(a), "l"(b)); return d;
}
__device__ __forceinline__ float2 up2(ull v) {
    float2 f; asm("mov.b64 {%0,%1},%2;" : "=f"(f.x), "=f"(f.y) : "l"(v)); return f;
}
__device__ __forceinline__ float ex2f(float x) {
    float y; asm("ex2.approx.ftz.f32 %0,%1;" : "=f"(y) : "f"(x)); return y;
}

// ---- tensor-core helpers (bf16 m16n8k16) ----
__device__ __forceinline__ void ldsm4(uint32_t* r, uint32_t a) {
    asm volatile("ldmatrix.sync.aligned.m8n8.x4.shared.b16 {%0,%1,%2,%3},[%4];"
        : "=r"(r[0]), "=r"(r[1]), "=r"(r[2]), "=r"(r[3]) : "r"(a));
}
__device__ __forceinline__ void ldsm2(uint32_t& b0, uint32_t& b1, uint32_t a) {
    asm volatile("ldmatrix.sync.aligned.m8n8.x2.shared.b16 {%0,%1},[%2];"
        : "=r"(b0), "=r"(b1) : "r"(a));
}
__device__ __forceinline__ void ldsm2t(uint32_t& b0, uint32_t& b1, uint32_t a) {
    asm volatile("ldmatrix.sync.aligned.m8n8.x2.trans.shared.b16 {%0,%1},[%2];"
        : "=r"(b0), "=r"(b1) : "r"(a));
}
__device__ __forceinline__ void mma16816(float* c, const uint32_t* a, uint32_t b0, uint32_t b1) {
    asm volatile("mma.sync.aligned.m16n8k16.row.col.f32.bf16.bf16.f32 "
        "{%0,%1,%2,%3},{%4,%5,%6,%7},{%8,%9},{%0,%1,%2,%3};"
        : "+f"(c[0]), "+f"(c[1]), "+f"(c[2]), "+f"(c[3])
        : "r"(a[0]), "r"(a[1]), "r"(a[2]), "r"(a[3]), "r"(b0), "r"(b1));
}

// ============================================================
// bf16 tensor-core NT GEMM with weight-split compensation:
// C[m,n] = sum_k A[m,k]*B[n,k] + bias[n]
// B (weights) staged as hi+lo bf16 pair (effective ~fp32 weights);
// A (activations) single bf16 (row-independent error, contracts).
// 256 threads, tile 128x64, K streamed in chunks of 32.
// ============================================================
__global__ void __launch_bounds__(256)
gemm_nt_bf16(const float* __restrict__ A, int lda,
             const float* __restrict__ B, int ldb,
             const float* __restrict__ bias,
             float* __restrict__ C, int ldc, int K)
{
    __shared__ __nv_bfloat16 As[128 * 40];
    __shared__ __nv_bfloat16 Bh[64 * 40];
    __shared__ __nv_bfloat16 Bl[64 * 40];
    int tid = threadIdx.x;
    int m0 = blockIdx.y * 128, n0 = blockIdx.x * 64;
    int w = tid >> 5, lane = tid & 31;
    int mw = (w & 3) * 32, nw = (w >> 2) * 32;

    uint32_t sbA = (uint32_t)__cvta_generic_to_shared(As);
    uint32_t sbBh = (uint32_t)__cvta_generic_to_shared(Bh);
    uint32_t sbBl = (uint32_t)__cvta_generic_to_shared(Bl);

    float cf[2][4][4];
#pragma unroll
    for (int mt = 0; mt < 2; mt++)
#pragma unroll
        for (int nt = 0; nt < 4; nt++) {
            cf[mt][nt][0] = 0.f; cf[mt][nt][1] = 0.f;
            cf[mt][nt][2] = 0.f; cf[mt][nt][3] = 0.f;
        }

    for (int k0 = 0; k0 < K; k0 += 32) {
        // stage A: 128 rows x 32 k (single bf16)
        for (int idx = tid; idx < 1024; idx += 256) {
            int m = idx >> 3, kg = idx & 7;
            float4 v = *(const float4*)&A[(long long)(m0 + m) * lda + k0 + kg * 4];
            __nv_bfloat162 p0 = __floats2bfloat162_rn(v.x, v.y);
            __nv_bfloat162 p1 = __floats2bfloat162_rn(v.z, v.w);
            uint2 pk; pk.x = *(uint32_t*)&p0; pk.y = *(uint32_t*)&p1;
            *(uint2*)&As[m * 40 + kg * 4] = pk;
        }
        // stage B: 64 rows x 32 k, hi + lo split
        for (int idx = tid; idx < 512; idx += 256) {
            int n = idx >> 3, kg = idx & 7;
            float4 v = *(const float4*)&B[(long long)(n0 + n) * ldb + k0 + kg * 4];
            __nv_bfloat16 hx = __float2bfloat16_rn(v.x);
            __nv_bfloat16 hy = __float2bfloat16_rn(v.y);
            __nv_bfloat16 hz = __float2bfloat16_rn(v.z);
            __nv_bfloat16 hw = __float2bfloat16_rn(v.w);
            __nv_bfloat162 h0; h0.x = hx; h0.y = hy;
            __nv_bfloat162 h1; h1.x = hz; h1.y = hw;
            uint2 ph; ph.x = *(uint32_t*)&h0; ph.y = *(uint32_t*)&h1;
            *(uint2*)&Bh[n * 40 + kg * 4] = ph;
            __nv_bfloat162 l0 = __floats2bfloat162_rn(v.x - __bfloat162float(hx),
                                                      v.y - __bfloat162float(hy));
            __nv_bfloat162 l1 = __floats2bfloat162_rn(v.z - __bfloat162float(hz),
                                                      v.w - __bfloat162float(hw));
            uint2 pl; pl.x = *(uint32_t*)&l0; pl.y = *(uint32_t*)&l1;
            *(uint2*)&Bl[n * 40 + kg * 4] = pl;
        }
        __syncthreads();

#pragma unroll
        for (int ks = 0; ks < 2; ks++) {
            uint32_t a0[4], a1[4];
            uint32_t aaddr = sbA + ((mw + (lane & 15)) * 40 + ks * 16 + (lane >> 4) * 8) * 2;
            ldsm4(a0, aaddr);
            ldsm4(a1, aaddr + 16 * 40 * 2);
            uint32_t boff = ((nw + (lane & 7)) * 40 + ks * 16 + ((lane >> 3) & 1) * 8) * 2;
#pragma unroll
            for (int nt = 0; nt < 4; nt++) {
                uint32_t b0, b1;
                ldsm2(b0, b1, sbBh + boff + nt * 8 * 40 * 2);
                mma16816(cf[0][nt], a0, b0, b1);
                mma16816(cf[1][nt], a1, b0, b1);
                ldsm2(b0, b1, sbBl + boff + nt * 8 * 40 * 2);
                mma16816(cf[0][nt], a0, b0, b1);
                mma16816(cf[1][nt], a1, b0, b1);
            }
        }
        __syncthreads();
    }
    // epilogue
#pragma unroll
    for (int mt = 0; mt < 2; mt++) {
        long long m = m0 + mw + mt * 16 + (lane >> 2);
#pragma unroll
        for (int nt = 0; nt < 4; nt++) {
            int n = n0 + nw + nt * 8 + (lane & 3) * 2;
            float bn0 = bias[n], bn1 = bias[n + 1];
            C[m * ldc + n]     = cf[mt][nt][0] + bn0;
            C[m * ldc + n + 1] = cf[mt][nt][1] + bn1;
            C[(m + 8) * ldc + n]     = cf[mt][nt][2] + bn0;
            C[(m + 8) * ldc + n + 1] = cf[mt][nt][3] + bn1;
        }
    }
}

// ============================================================
// Generic batched NT GEMM (fp32, R12 version) — used for Gx only.
// ============================================================
template <int BN>
__global__ void gemm_nt_flex(
    const float* __restrict__ A, int Am, long long zA1, int zA2,
    const float* __restrict__ B, int Bn, int Bk, long long zB1, int zB2,
    const float* __restrict__ bias,
    float* __restrict__ C, int Cld, long long zC1, int zC2,
    int M, int N, int K, float alpha)
{
    constexpr int TM = 64, TK = 16;
    constexpr int TX = BN / 4;
    constexpr int TPB = TX * 16;
    constexpr int NA = TM * TK / TPB;
    constexpr int NB = BN * TK / TPB;
    __shared__ float As[TK][TM + 4];
    __shared__ float Bs[TK][BN + 4];

    int z = blockIdx.z;
    const float* Ab = A + (long long)(z >> 2) * zA1 + (long long)(z & 3) * zA2;
    const float* Bb = B + (long long)(z >> 2) * zB1 + (long long)(z & 3) * zB2;
    float* Cb = C + (long long)(z >> 2) * zC1 + (long long)(z & 3) * zC2;

    int tid = threadIdx.x;
    int tx = tid % TX, ty = tid / TX;
    int m0 = blockIdx.y * TM, n0 = blockIdx.x * BN;

    float aR[NA], bR[NB];

#pragma unroll
    for (int j = 0; j < NA; j++) {
        int i = tid + j * TPB; int m = i >> 4, k = i & 15;
        aR[j] = Ab[(long long)(m0 + m) * Am + k];
    }
    if (Bk == 1) {
#pragma unroll
        for (int j = 0; j < NB; j++) {
            int i = tid + j * TPB; int n = i >> 4, k = i & 15;
            bR[j] = (n0 + n < N) ? Bb[(long long)(n0 + n) * Bn + k] : 0.f;
        }
    } else {
#pragma unroll
        for (int j = 0; j < NB; j++) {
            int i = tid + j * TPB; int n = i % BN, k = i / BN;
            bR[j] = (n0 + n < N) ? Bb[(long long)(n0 + n) * Bn + (long long)k * Bk] : 0.f;
        }
    }

    ull acc2[4][2] = {};
    for (int k0 = 0; k0 < K; k0 += TK) {
#pragma unroll
        for (int j = 0; j < NA; j++) {
            int i = tid + j * TPB; int m = i >> 4, k = i & 15;
            As[k][m] = aR[j];
        }
        if (Bk == 1) {
#pragma unroll
            for (int j = 0; j < NB; j++) {
                int i = tid + j * TPB; int n = i >> 4, k = i & 15;
                Bs[k][n] = bR[j];
            }
        } else {
#pragma unroll
            for (int j = 0; j < NB; j++) {
                int i = tid + j * TPB; int n = i % BN, k = i / BN;
                Bs[k][n] = bR[j];
            }
        }
        __syncthreads();

        int k1 = k0 + TK;
        if (k1 < K) {
#pragma unroll
            for (int j = 0; j < NA; j++) {
                int i = tid + j * TPB; int m = i >> 4, k = i & 15;
                aR[j] = Ab[(long long)(m0 + m) * Am + k1 + k];
            }
            if (Bk == 1) {
#pragma unroll
                for (int j = 0; j < NB; j++) {
                    int i = tid + j * TPB; int n = i >> 4, k = i & 15;
                    bR[j] = (n0 + n < N) ? Bb[(long long)(n0 + n) * Bn + k1 + k] : 0.f;
                }
            } else {
#pragma unroll
                for (int j = 0; j < NB; j++) {
                    int i = tid + j * TPB; int n = i % BN, k = i / BN;
                    bR[j] = (n0 + n < N) ? Bb[(long long)(n0 + n) * Bn + (long long)(k1 + k) * Bk] : 0.f;
                }
            }
        }

#pragma unroll
        for (int kk = 0; kk < TK; kk++) {
            float4 a4 = *(const float4*)&As[kk][ty * 4];
            float4 b4 = *(const float4*)&Bs[kk][tx * 4];
            ull bp0 = pk2(b4.x, b4.y), bp1 = pk2(b4.z, b4.w);
            float a[4] = {a4.x, a4.y, a4.z, a4.w};
#pragma unroll
            for (int i = 0; i < 4; i++) {
                ull aa = pk2(a[i], a[i]);
                acc2[i][0] = fma2(aa, bp0, acc2[i][0]);
                acc2[i][1] = fma2(aa, bp1, acc2[i][1]);
            }
        }
        __syncthreads();
    }
#pragma unroll
    for (int i = 0; i < 4; i++) {
        long long m = m0 + ty * 4 + i;
#pragma unroll
        for (int jp = 0; jp < 2; jp++) {
            float2 f = up2(acc2[i][jp]);
            int n = n0 + tx * 4 + 2 * jp;
            if (n < N)     Cb[m * Cld + n]     = alpha * f.x + (bias ? bias[n] : 0.f);
            if (n + 1 < N) Cb[m * Cld + n + 1] = alpha * f.y + (bias ? bias[n + 1] : 0.f);
        }
    }
}

// ============================================================
// Sequential sLSTM scan (R12 version, unchanged)
// ============================================================
__global__ void __launch_bounds__(512, 1)
scan_kernel(const float* __restrict__ Wcell, const float* __restrict__ Gx,
            float* __restrict__ seqh)
{
    extern __shared__ float2 ws2[];
    __shared__ float h_s[128], c_s[128], n_s[128], gates_s[512];
    int tid = threadIdx.x, b = blockIdx.x;

    ull wr2[48];
    {
        const float4* wrow = (const float4*)(Wcell + tid * 192 + 64);
#pragma unroll
        for (int c = 0; c < 24; c++) {
            float4 w = wrow[c];
            wr2[2 * c] = pk2(w.x, w.y);
            wr2[2 * c + 1] = pk2(w.z, w.w);
        }
    }
#pragma unroll
    for (int p = 0; p < 16; p++)
        ws2[p * 512 + tid] = make_float2(Wcell[tid * 192 + 160 + 2 * p],
                                         Wcell[tid * 192 + 160 + 2 * p + 1]);
    if (tid < 128) { h_s[tid] = 0.f; c_s[tid] = 0.f; n_s[tid] = 1.f; }
    __syncthreads();

    long long gbase = (long long)b * 512 * 512 + tid;
    long long hbase = (long long)b * 512 * 128;
    float gx = Gx[gbase];

    for (int t = 0; t < 512; t++) {
        float gx_next = (t < 511) ? Gx[gbase + (long long)(t + 1) * 512] : 0.f;
        ull a0 = pk2(gx, 0.f), a1 = pk2(0.f, 0.f);
#pragma unroll
        for (int c = 0; c < 24; c++) {
            float4 h4 = *(const float4*)&h_s[c * 4];
            a0 = fma2(wr2[2 * c],     pk2(h4.x, h4.y), a0);
            a1 = fma2(wr2[2 * c + 1], pk2(h4.z, h4.w), a1);
        }
#pragma unroll
        for (int c = 0; c < 8; c++) {
            float4 h4 = *(const float4*)&h_s[96 + c * 4];
            ull wA = *(const ull*)&ws2[(2 * c) * 512 + tid];
            ull wB = *(const ull*)&ws2[(2 * c + 1) * 512 + tid];
            a0 = fma2(wA, pk2(h4.x, h4.y), a0);
            a1 = fma2(wB, pk2(h4.z, h4.w), a1);
        }
        float2 f0 = up2(a0), f1 = up2(a1);
        gates_s[tid] = (f0.x + f0.y) + (f1.x + f1.y);
        __syncthreads();
        if (tid < 128) {
            float gi = gates_s[tid], gf = gates_s[tid + 128];
            float go = gates_s[tid + 256], gz = gates_s[tid + 384];
            float ii = __expf(fminf(fmaxf(gi, -5.f), 5.f));
            float ff = __expf(fminf(fmaxf(gf, -5.f), 5.f));
            float cc = fmaf(ff, c_s[tid], ii * __tanhf(gz));
            cc = fminf(fmaxf(cc, -1e6f), 1e6f);
            float nn = fminf(fmaxf(fmaf(ff, n_s[tid], ii), 1e-6f), 1e6f);
            float sig = __frcp_rn(1.f + __expf(-go));
            float hh = __fdividef(cc, nn) * sig;
            if (!isfinite(hh)) hh = 0.f;
            c_s[tid] = cc; n_s[tid] = nn; h_s[tid] = hh;
            seqh[hbase + (long long)t * 128 + tid] = hh;
        }
        __syncthreads();
        gx = gx_next;
    }
}

// ============================================================
// Fused flash attention v6 (R14 version, unchanged)
// ============================================================
__global__ void __launch_bounds__(256, 3)
flash_kernel(const float* __restrict__ qkv, float* __restrict__ av)
{
    extern __shared__ char smraw[];
    __nv_bfloat16* Qs = (__nv_bfloat16*)(smraw);
    __nv_bfloat16* Ks = (__nv_bfloat16*)(smraw + 10240);
    __nv_bfloat16* Vs = (__nv_bfloat16*)(smraw + 15360);
    __nv_bfloat16* Ps = (__nv_bfloat16*)(smraw + 20480);
    float* rowM = (float*)(smraw + 38912);
    float* rowL = (float*)(smraw + 39424);
    float* rowS = (float*)(smraw + 39936);

    int tid = threadIdx.x;
    int qt = blockIdx.x;
    int bh = blockIdx.y;
    int b = bh >> 2;
    int h = bh & 3;
    long long base = (long long)b * 512 * 384 + h * 32;
    int q0 = qt * 128;
    const float alpha = 0.25501398f;

    for (int idx = tid; idx < 1024; idx += 256) {
        int s = idx >> 3;
        int dg = idx & 7;
        float4 v = *(const float4*)&qkv[base + (long long)(q0 + s) * 384 + dg * 4];
        __nv_bfloat162 p0 = __floats2bfloat162_rn(v.x * alpha, v.y * alpha);
        __nv_bfloat162 p1 = __floats2bfloat162_rn(v.z * alpha, v.w * alpha);
        uint2 pk; pk.x = *(uint32_t*)&p0; pk.y = *(uint32_t*)&p1;
        *(uint2*)&Qs[s * 40 + dg * 4] = pk;
    }
    if (tid < 128) { rowM[tid] = -1e30f; rowL[tid] = 0.f; }
    __syncthreads();

    int w = tid >> 5;
    int lane = tid & 31;
    uint32_t sb = (uint32_t)__cvta_generic_to_shared(smraw);

    uint32_t aq0[4];
    uint32_t aq1[4];
    {
        uint32_t qaddr = sb + ((16 * w + (lane & 15)) * 40 + (lane >> 4) * 8) * 2;
        ldsm4(aq0, qaddr);
        ldsm4(aq1, qaddr + 32);
    }

    int qA = 16 * w + (lane >> 2);
    int qB = qA + 8;
    float of[4][4];
#pragma unroll
    for (int i = 0; i < 4; i++) {
        of[i][0] = 0.f; of[i][1] = 0.f; of[i][2] = 0.f; of[i][3] = 0.f;
    }

    for (int kt = 0; kt < 8; kt++) {
        int kbase = kt * 64;
        for (int idx = tid; idx < 512; idx += 256) {
            int s = idx >> 3;
            int dg = idx & 7;
            long long grow = base + (long long)(kbase + s) * 384 + dg * 4;
            float4 kv = *(const float4*)&qkv[grow + 128];
            float4 vv = *(const float4*)&qkv[grow + 256];
            __nv_bfloat162 k0 = __floats2bfloat162_rn(kv.x, kv.y);
            __nv_bfloat162 k1 = __floats2bfloat162_rn(kv.z, kv.w);
            uint2 kk; kk.x = *(uint32_t*)&k0; kk.y = *(uint32_t*)&k1;
            *(uint2*)&Ks[s * 40 + dg * 4] = kk;
            __nv_bfloat162 v0 = __floats2bfloat162_rn(vv.x, vv.y);
            __nv_bfloat162 v1 = __floats2bfloat162_rn(vv.z, vv.w);
            uint2 vp; vp.x = *(uint32_t*)&v0; vp.y = *(uint32_t*)&v1;
            *(uint2*)&Vs[s * 40 + dg * 4] = vp;
        }
        __syncthreads();

        float cf[8][4];
#pragma unroll
        for (int nt = 0; nt < 8; nt++) {
            cf[nt][0] = 0.f; cf[nt][1] = 0.f; cf[nt][2] = 0.f; cf[nt][3] = 0.f;
        }
        uint32_t kaddr0 = sb + 10240 + ((lane & 7) * 40 + ((lane >> 3) & 1) * 8) * 2;
#pragma unroll
        for (int nt = 0; nt < 8; nt++) {
            uint32_t addr = kaddr0 + nt * 640;
            uint32_t b0, b1;
            ldsm2(b0, b1, addr);
            mma16816(cf[nt], aq0, b0, b1);
            ldsm2(b0, b1, addr + 32);
            mma16816(cf[nt], aq1, b0, b1);
        }

        float moA = rowM[qA];
        float moB = rowM[qB];
        float mxA = cf[0][0];
        float mxB = cf[0][2];
#pragma unroll
        for (int nt = 0; nt < 8; nt++) {
            mxA = fmaxf(mxA, fmaxf(cf[nt][0], cf[nt][1]));
            mxB = fmaxf(mxB, fmaxf(cf[nt][2], cf[nt][3]));
        }
        mxA = fmaxf(mxA, __shfl_xor_sync(0xffffffffu, mxA, 1));
        mxA = fmaxf(mxA, __shfl_xor_sync(0xffffffffu, mxA, 2));
        mxB = fmaxf(mxB, __shfl_xor_sync(0xffffffffu, mxB, 1));
        mxB = fmaxf(mxB, __shfl_xor_sync(0xffffffffu, mxB, 2));
        float mnA = fmaxf(moA, mxA);
        float mnB = fmaxf(moB, mxB);
        float sumA = 0.f, sumB = 0.f;
        int colo = (lane & 3) * 2;
#pragma unroll
        for (int nt = 0; nt < 8; nt++) {
            float e0 = ex2f(cf[nt][0] - mnA);
            float e1 = ex2f(cf[nt][1] - mnA);
            float e2 = ex2f(cf[nt][2] - mnB);
            float e3 = ex2f(cf[nt][3] - mnB);
            sumA += e0 + e1;
            sumB += e2 + e3;
            __nv_bfloat162 pa = __floats2bfloat162_rn(e0, e1);
            __nv_bfloat162 pb = __floats2bfloat162_rn(e2, e3);
            *(uint32_t*)&Ps[qA * 72 + nt * 8 + colo] = *(uint32_t*)&pa;
            *(uint32_t*)&Ps[qB * 72 + nt * 8 + colo] = *(uint32_t*)&pb;
        }
        sumA += __shfl_xor_sync(0xffffffffu, sumA, 1);
        sumA += __shfl_xor_sync(0xffffffffu, sumA, 2);
        sumB += __shfl_xor_sync(0xffffffffu, sumB, 1);
        sumB += __shfl_xor_sync(0xffffffffu, sumB, 2);
        if ((lane & 3) == 0) {
            float scA = ex2f(moA - mnA);
            float scB = ex2f(moB - mnB);
            rowS[qA] = scA; rowM[qA] = mnA; rowL[qA] = rowL[qA] * scA + sumA;
            rowS[qB] = scB; rowM[qB] = mnB; rowL[qB] = rowL[qB] * scB + sumB;
        }
        __syncwarp();

        {
            float scA = rowS[qA];
            float scB = rowS[qB];
#pragma unroll
            for (int i = 0; i < 4; i++) {
                of[i][0] *= scA; of[i][1] *= scA;
                of[i][2] *= scB; of[i][3] *= scB;
            }
        }
        uint32_t paddr0 = sb + 20480 + ((16 * w + (lane & 15)) * 72 + (lane >> 4) * 8) * 2;
        uint32_t vaddr0 = sb + 15360 + ((lane & 15) * 40) * 2;
#pragma unroll
        for (int ks = 0; ks < 4; ks++) {
            uint32_t ap[4];
            ldsm4(ap, paddr0 + ks * 32);
#pragma unroll
            for (int nt2 = 0; nt2 < 4; nt2++) {
                uint32_t b0, b1;
                ldsm2t(b0, b1, vaddr0 + ks * 1280 + nt2 * 16);
                mma16816(of[nt2], ap, b0, b1);
            }
        }
        __syncthreads();
    }

    {
        float iA = 1.f / rowL[qA];
        float iB = 1.f / rowL[qB];
        long long orA = (long long)(b * 512 + q0 + qA) * 128 + h * 32 + (lane & 3) * 2;
        long long orB = orA + 8LL * 128;
#pragma unroll
        for (int nt2 = 0; nt2 < 4; nt2++) {
            float2 ra; ra.x = of[nt2][0] * iA; ra.y = of[nt2][1] * iA;
            float2 rb; rb.x = of[nt2][2] * iB; rb.y = of[nt2][3] * iB;
            *(float2*)&av[orA + nt2 * 8] = ra;
            *(float2*)&av[orB + nt2 * 8] = rb;
        }
    }
}

// ============================================================
// Reductions (128-thread blocks)
// ============================================================
__device__ __forceinline__ float2 blockReduce2(float a, float b, float2* sh)
{
#pragma unroll
    for (int o = 16; o; o >>= 1) {
        a += __shfl_xor_sync(0xffffffffu, a, o);
        b += __shfl_xor_sync(0xffffffffu, b, o);
    }
    int w = threadIdx.x >> 5;
    if ((threadIdx.x & 31) == 0) sh[w] = make_float2(a, b);
    __syncthreads();
    float2 r;
    r.x = sh[0].x + sh[1].x + sh[2].x + sh[3].x;
    r.y = sh[0].y + sh[1].y + sh[2].y + sh[3].y;
    __syncthreads();
    return r;
}

__global__ void zero_ctx_kernel(float* ctx) { ctx[blockIdx.x * 128 + threadIdx.x] = 0.f; }

__global__ void ln_mean_kernel(const float* __restrict__ seqh, const float* __restrict__ ao,
                               const float* __restrict__ g, const float* __restrict__ bln,
                               float* __restrict__ ctx)
{
    __shared__ float2 sh[4];
    int b = blockIdx.x >> 5, chunk = blockIdx.x & 31;
    int tid = threadIdx.x;
    float acc = 0.f;
    for (int r = 0; r < 16; r++) {
        long long row = ((long long)b * 512 + chunk * 16 + r) * 128;
        float y = seqh[row + tid] + ao[row + tid];
        float2 ss = blockReduce2(y, y * y, sh);
        float mean = ss.x * (1.f / 128.f);
        float var = ss.y * (1.f / 128.f) - mean * mean;
        acc += g[tid] * (y - mean) * rsqrtf(var + 1e-5f) + bln[tid];
    }
    atomicAdd(&ctx[b * 128 + tid], acc);
}

__global__ void heads_kernel(const float* __restrict__ ctx, const float* __restrict__ info,
    const float* __restrict__ Wa1, const float* __restrict__ ba1,
    const float* __restrict__ lna_g, const float* __restrict__ lna_b,
    const float* __restrict__ Wa2, const float* __restrict__ ba2,
    const float* __restrict__ Wc1, const float* __restrict__ bc1,
    const float* __restrict__ lnc_g, const float* __restrict__ lnc_b,
    const float* __restrict__ Wc2, const float* __restrict__ bc2,
    float* __restrict__ out)
{
    __shared__ float comb[144];
    __shared__ float ra[128], rc[128];
    __shared__ float logit[3];
    __shared__ float2 sh[4];
    int b = blockIdx.x, tid = threadIdx.x;
    comb[tid] = ctx[b * 128 + tid] * (1.f / 512.f);
    if (tid < 16) comb[128 + tid] = (tid < 13) ? info[b * 13 + tid] : 0.f;
    __syncthreads();

    float sa = ba1[tid], sc = bc1[tid];
    for (int k = 0; k < 141; k++) {
        sa = fmaf(Wa1[tid * 141 + k], comb[k], sa);
        sc = fmaf(Wc1[tid * 141 + k], comb[k], sc);
    }
    float2 r2 = blockReduce2(sa, sa * sa, sh);
    float ma = r2.x * (1.f / 128.f), va = r2.y * (1.f / 128.f) - ma * ma;
    ra[tid] = fmaxf(lna_g[tid] * (sa - ma) * rsqrtf(va + 1e-5f) + lna_b[tid], 0.f);
    r2 = blockReduce2(sc, sc * sc, sh);
    float mc = r2.x * (1.f / 128.f), vc = r2.y * (1.f / 128.f) - mc * mc;
    rc[tid] = fmaxf(lnc_g[tid] * (sc - mc) * rsqrtf(vc + 1e-5f) + lnc_b[tid], 0.f);
    __syncthreads();

    if (tid < 3) {
        float l = ba2[tid];
        for (int k = 0; k < 128; k++) l = fmaf(Wa2[tid * 128 + k], ra[k], l);
        logit[tid] = l;
    }
    float2 vv = blockReduce2(rc[tid] * Wc2[tid], 0.f, sh);
    if (tid == 0) out[192 + b] = vv.x + bc2[0];
    __syncthreads();
    if (tid == 0) {
        float m = fmaxf(logit[0], fmaxf(logit[1], logit[2]));
        float e0 = expf(logit[0] - m), e1 = expf(logit[1] - m), e2 = expf(logit[2] - m);
        float inv = 1.f / (e0 + e1 + e2);
        out[b * 3 + 0] = e0 * inv;
        out[b * 3 + 1] = e1 * inv;
        out[b * 3 + 2] = e2 * inv;
    }
}

// ============================================================
extern "C" void kernel_launch(void* const* d_in, const int* in_sizes, int n_in,
                              void* d_out, int out_size)
{
    const float* x      = (const float*)d_in[0];
    const float* info   = (const float*)d_in[1];
    const float* W_cell = (const float*)d_in[2];
    const float* b_cell = (const float*)d_in[3];
    const float* Wqkv   = (const float*)d_in[4];
    const float* bqkv   = (const float*)d_in[5];
    const float* Wo     = (const float*)d_in[6];
    const float* bo     = (const float*)d_in[7];
    const float* ln_g   = (const float*)d_in[8];
    const float* ln_b   = (const float*)d_in[9];
    const float* Wa1    = (const float*)d_in[10];
    const float* ba1    = (const float*)d_in[11];
    const float* lna_g  = (const float*)d_in[12];
    const float* lna_b  = (const float*)d_in[13];
    const float* Wa2    = (const float*)d_in[14];
    const float* ba2    = (const float*)d_in[15];
    const float* Wc1    = (const float*)d_in[16];
    const float* bc1    = (const float*)d_in[17];
    const float* lnc_g  = (const float*)d_in[18];
    const float* lnc_b  = (const float*)d_in[19];
    const float* Wc2    = (const float*)d_in[20];
    const float* bc2    = (const float*)d_in[21];
    float* out = (float*)d_out;
    (void)in_sizes; (void)n_in; (void)out_size;

    float *pGx, *pSeqh, *pQkv, *pAv, *pAo, *pCtx;
    cudaGetSymbolAddress((void**)&pGx, g_Gx);
    cudaGetSymbolAddress((void**)&pSeqh, g_seqh);
    cudaGetSymbolAddress((void**)&pQkv, g_qkv);
    cudaGetSymbolAddress((void**)&pAv, g_av);
    cudaGetSymbolAddress((void**)&pAo, g_attnout);
    cudaGetSymbolAddress((void**)&pCtx, g_ctx);

    cudaFuncSetAttribute(scan_kernel, cudaFuncAttributeMaxDynamicSharedMemorySize, 72 * 1024);
    cudaFuncSetAttribute(flash_kernel, cudaFuncAttributeMaxDynamicSharedMemorySize, 40448);

    // 1) Gx = x @ Wcell[:, :64]^T + b_cell            (fp32; feeds recurrence)
    gemm_nt_flex<64><<<dim3(8, 512, 1), 256>>>(
        x, 64, 0, 0, W_cell, 192, 1, 0, 0, b_cell, pGx, 512, 0, 0, 32768, 512, 64, 1.f);

    // 2) sequential scan -> seqh
    scan_kernel<<<64, 512, 16 * 512 * sizeof(float2)>>>(W_cell, pGx, pSeqh);

    // 3) qkv = seqh @ Wqkv^T + bqkv                   (bf16 TC, weight-split)
    gemm_nt_bf16<<<dim3(6, 256), 256>>>(pSeqh, 128, Wqkv, 128, bqkv, pQkv, 384, 128);

    // 4) fused attention v6 (bf16 tensor cores)
    flash_kernel<<<dim3(4, 256), 256, 40448>>>(pQkv, pAv);

    // 5) attn_out = av @ Wo^T + bo                    (bf16 TC, weight-split)
    gemm_nt_bf16<<<dim3(2, 256), 256>>>(pAv, 128, Wo, 128, bo, pAo, 128, 128);

    // 6) context = mean_s LN(seqh + attn_out)
    zero_ctx_kernel<<<64, 128>>>(pCtx);
    ln_mean_kernel<<<2048, 128>>>(pSeqh, pAo, ln_g, ln_b, pCtx);

    // 7) heads
    heads_kernel<<<64, 128>>>(pCtx, info, Wa1, ba1, lna_g, lna_b, Wa2, ba2,
                              Wc1, bc1, lnc_g, lnc_b, Wc2, bc2, out);
}

// round 17
// speedup vs baseline: 1.5044x; 1.0313x over previous
#include <cuda_runtime.h>
#include <cuda_fp16.h>
#include <cuda_bf16.h>
#include <stdint.h>
#include <math.h>

typedef unsigned long long ull;

// Problem constants: B=64, S=512, D=64, H=128, HEADS=4, HD=32, I=13, A=3

// -------- scratch (device globals; no allocation) --------
__device__ float g_Gx[32768 * 512];
__device__ float g_seqh[32768 * 128];
__device__ float g_qkv[32768 * 384 + 64];
__device__ float g_av[32768 * 128];
__device__ float g_attnout[32768 * 128];
__device__ float g_ctx[64 * 128];

// ---- packed f32x2 helpers ----
__device__ __forceinline__ ull pk2(float a, float b) {
    ull r; asm("mov.b64 %0,{%1,%2};" : "=l"(r) : "f"(a), "f"(b)); return r;
}
__device__ __forceinline__ ull fma2(ull a, ull b, ull c) {
    ull d; asm("fma.rn.f32x2 %0,%1,%2,%3;" : "=l"(d) : "l"(a), "l"(b), "l"(c)); return d;
}
__device__ __forceinline__ ull mul2(ull a, ull b) {
    ull d; asm("mul.rn.f32x2 %0,%1,%2;" : "=l"(d) : "l"(a), "l"(b)); return d;
}
__device__ __forceinline__ float2 up2(ull v) {
    float2 f; asm("mov.b64 {%0,%1},%2;" : "=f"(f.x), "=f"(f.y) : "l"(v)); return f;
}
__device__ __forceinline__ float ex2f(float x) {
    float y; asm("ex2.approx.ftz.f32 %0,%1;" : "=f"(y) : "f"(x)); return y;
}

// ---- tensor-core helpers (bf16 m16n8k16) ----
__device__ __forceinline__ void ldsm4(uint32_t* r, uint32_t a) {
    asm volatile("ldmatrix.sync.aligned.m8n8.x4.shared.b16 {%0,%1,%2,%3},[%4];"
        : "=r"(r[0]), "=r"(r[1]), "=r"(r[2]), "=r"(r[3]) : "r"(a));
}
__device__ __forceinline__ void ldsm2(uint32_t& b0, uint32_t& b1, uint32_t a) {
    asm volatile("ldmatrix.sync.aligned.m8n8.x2.shared.b16 {%0,%1},[%2];"
        : "=r"(b0), "=r"(b1) : "r"(a));
}
__device__ __forceinline__ void ldsm2t(uint32_t& b0, uint32_t& b1, uint32_t a) {
    asm volatile("ldmatrix.sync.aligned.m8n8.x2.trans.shared.b16 {%0,%1},[%2];"
        : "=r"(b0), "=r"(b1) : "r"(a));
}
__device__ __forceinline__ void mma16816(float* c, const uint32_t* a, uint32_t b0, uint32_t b1) {
    asm volatile("mma.sync.aligned.m16n8k16.row.col.f32.bf16.bf16.f32 "
        "{%0,%1,%2,%3},{%4,%5,%6,%7},{%8,%9},{%0,%1,%2,%3};"
        : "+f"(c[0]), "+f"(c[1]), "+f"(c[2]), "+f"(c[3])
        : "r"(a[0]), "r"(a[1]), "r"(a[2]), "r"(a[3]), "r"(b0), "r"(b1));
}

// ============================================================
// bf16 TC NT GEMM, weight-split (2-term): post-scan GEMMs.
// C[m,n] = sum_k A[m,k]*B[n,k] + bias[n]
// ============================================================
__global__ void __launch_bounds__(256)
gemm_nt_bf16(const float* __restrict__ A, int lda,
             const float* __restrict__ B, int ldb,
             const float* __restrict__ bias,
             float* __restrict__ C, int ldc, int K)
{
    __shared__ __nv_bfloat16 As[128 * 40];
    __shared__ __nv_bfloat16 Bh[64 * 40];
    __shared__ __nv_bfloat16 Bl[64 * 40];
    int tid = threadIdx.x;
    int m0 = blockIdx.y * 128, n0 = blockIdx.x * 64;
    int w = tid >> 5, lane = tid & 31;
    int mw = (w & 3) * 32, nw = (w >> 2) * 32;

    uint32_t sbA = (uint32_t)__cvta_generic_to_shared(As);
    uint32_t sbBh = (uint32_t)__cvta_generic_to_shared(Bh);
    uint32_t sbBl = (uint32_t)__cvta_generic_to_shared(Bl);

    float cf[2][4][4];
#pragma unroll
    for (int mt = 0; mt < 2; mt++)
#pragma unroll
        for (int nt = 0; nt < 4; nt++) {
            cf[mt][nt][0] = 0.f; cf[mt][nt][1] = 0.f;
            cf[mt][nt][2] = 0.f; cf[mt][nt][3] = 0.f;
        }

    for (int k0 = 0; k0 < K; k0 += 32) {
        for (int idx = tid; idx < 1024; idx += 256) {
            int m = idx >> 3, kg = idx & 7;
            float4 v = *(const float4*)&A[(long long)(m0 + m) * lda + k0 + kg * 4];
            __nv_bfloat162 p0 = __floats2bfloat162_rn(v.x, v.y);
            __nv_bfloat162 p1 = __floats2bfloat162_rn(v.z, v.w);
            uint2 pk; pk.x = *(uint32_t*)&p0; pk.y = *(uint32_t*)&p1;
            *(uint2*)&As[m * 40 + kg * 4] = pk;
        }
        for (int idx = tid; idx < 512; idx += 256) {
            int n = idx >> 3, kg = idx & 7;
            float4 v = *(const float4*)&B[(long long)(n0 + n) * ldb + k0 + kg * 4];
            __nv_bfloat16 hx = __float2bfloat16_rn(v.x);
            __nv_bfloat16 hy = __float2bfloat16_rn(v.y);
            __nv_bfloat16 hz = __float2bfloat16_rn(v.z);
            __nv_bfloat16 hw = __float2bfloat16_rn(v.w);
            __nv_bfloat162 h0; h0.x = hx; h0.y = hy;
            __nv_bfloat162 h1; h1.x = hz; h1.y = hw;
            uint2 ph; ph.x = *(uint32_t*)&h0; ph.y = *(uint32_t*)&h1;
            *(uint2*)&Bh[n * 40 + kg * 4] = ph;
            __nv_bfloat162 l0 = __floats2bfloat162_rn(v.x - __bfloat162float(hx),
                                                      v.y - __bfloat162float(hy));
            __nv_bfloat162 l1 = __floats2bfloat162_rn(v.z - __bfloat162float(hz),
                                                      v.w - __bfloat162float(hw));
            uint2 pl; pl.x = *(uint32_t*)&l0; pl.y = *(uint32_t*)&l1;
            *(uint2*)&Bl[n * 40 + kg * 4] = pl;
        }
        __syncthreads();

#pragma unroll
        for (int ks = 0; ks < 2; ks++) {
            uint32_t a0[4], a1[4];
            uint32_t aaddr = sbA + ((mw + (lane & 15)) * 40 + ks * 16 + (lane >> 4) * 8) * 2;
            ldsm4(a0, aaddr);
            ldsm4(a1, aaddr + 16 * 40 * 2);
            uint32_t boff = ((nw + (lane & 7)) * 40 + ks * 16 + ((lane >> 3) & 1) * 8) * 2;
#pragma unroll
            for (int nt = 0; nt < 4; nt++) {
                uint32_t b0, b1;
                ldsm2(b0, b1, sbBh + boff + nt * 8 * 40 * 2);
                mma16816(cf[0][nt], a0, b0, b1);
                mma16816(cf[1][nt], a1, b0, b1);
                ldsm2(b0, b1, sbBl + boff + nt * 8 * 40 * 2);
                mma16816(cf[0][nt], a0, b0, b1);
                mma16816(cf[1][nt], a1, b0, b1);
            }
        }
        __syncthreads();
    }
#pragma unroll
    for (int mt = 0; mt < 2; mt++) {
        long long m = m0 + mw + mt * 16 + (lane >> 2);
#pragma unroll
        for (int nt = 0; nt < 4; nt++) {
            int n = n0 + nw + nt * 8 + (lane & 3) * 2;
            float bn0 = bias[n], bn1 = bias[n + 1];
            C[m * ldc + n]     = cf[mt][nt][0] + bn0;
            C[m * ldc + n + 1] = cf[mt][nt][1] + bn1;
            C[(m + 8) * ldc + n]     = cf[mt][nt][2] + bn0;
            C[(m + 8) * ldc + n + 1] = cf[mt][nt][3] + bn1;
        }
    }
}

// ============================================================
// bf16 TC NT GEMM, dual split (3-term: AhBh + AhBl + AlBh).
// Effective ~fp32 precision on both operands — used for Gx,
// which feeds the sequential recurrence.
// ============================================================
__global__ void __launch_bounds__(256)
gemm_nt_bf16_split3(const float* __restrict__ A, int lda,
                    const float* __restrict__ B, int ldb,
                    const float* __restrict__ bias,
                    float* __restrict__ C, int ldc, int K)
{
    __shared__ __nv_bfloat16 Ah[128 * 40];
    __shared__ __nv_bfloat16 Al[128 * 40];
    __shared__ __nv_bfloat16 Bh[64 * 40];
    __shared__ __nv_bfloat16 Bl[64 * 40];
    int tid = threadIdx.x;
    int m0 = blockIdx.y * 128, n0 = blockIdx.x * 64;
    int w = tid >> 5, lane = tid & 31;
    int mw = (w & 3) * 32, nw = (w >> 2) * 32;

    uint32_t sbAh = (uint32_t)__cvta_generic_to_shared(Ah);
    uint32_t sbAl = (uint32_t)__cvta_generic_to_shared(Al);
    uint32_t sbBh = (uint32_t)__cvta_generic_to_shared(Bh);
    uint32_t sbBl = (uint32_t)__cvta_generic_to_shared(Bl);

    float cf[2][4][4];
#pragma unroll
    for (int mt = 0; mt < 2; mt++)
#pragma unroll
        for (int nt = 0; nt < 4; nt++) {
            cf[mt][nt][0] = 0.f; cf[mt][nt][1] = 0.f;
            cf[mt][nt][2] = 0.f; cf[mt][nt][3] = 0.f;
        }

    for (int k0 = 0; k0 < K; k0 += 32) {
        // stage A hi/lo
        for (int idx = tid; idx < 1024; idx += 256) {
            int m = idx >> 3, kg = idx & 7;
            float4 v = *(const float4*)&A[(long long)(m0 + m) * lda + k0 + kg * 4];
            __nv_bfloat16 hx = __float2bfloat16_rn(v.x);
            __nv_bfloat16 hy = __float2bfloat16_rn(v.y);
            __nv_bfloat16 hz = __float2bfloat16_rn(v.z);
            __nv_bfloat16 hw = __float2bfloat16_rn(v.w);
            __nv_bfloat162 h0; h0.x = hx; h0.y = hy;
            __nv_bfloat162 h1; h1.x = hz; h1.y = hw;
            uint2 ph; ph.x = *(uint32_t*)&h0; ph.y = *(uint32_t*)&h1;
            *(uint2*)&Ah[m * 40 + kg * 4] = ph;
            __nv_bfloat162 l0 = __floats2bfloat162_rn(v.x - __bfloat162float(hx),
                                                      v.y - __bfloat162float(hy));
            __nv_bfloat162 l1 = __floats2bfloat162_rn(v.z - __bfloat162float(hz),
                                                      v.w - __bfloat162float(hw));
            uint2 pl; pl.x = *(uint32_t*)&l0; pl.y = *(uint32_t*)&l1;
            *(uint2*)&Al[m * 40 + kg * 4] = pl;
        }
        // stage B hi/lo
        for (int idx = tid; idx < 512; idx += 256) {
            int n = idx >> 3, kg = idx & 7;
            float4 v = *(const float4*)&B[(long long)(n0 + n) * ldb + k0 + kg * 4];
            __nv_bfloat16 hx = __float2bfloat16_rn(v.x);
            __nv_bfloat16 hy = __float2bfloat16_rn(v.y);
            __nv_bfloat16 hz = __float2bfloat16_rn(v.z);
            __nv_bfloat16 hw = __float2bfloat16_rn(v.w);
            __nv_bfloat162 h0; h0.x = hx; h0.y = hy;
            __nv_bfloat162 h1; h1.x = hz; h1.y = hw;
            uint2 ph; ph.x = *(uint32_t*)&h0; ph.y = *(uint32_t*)&h1;
            *(uint2*)&Bh[n * 40 + kg * 4] = ph;
            __nv_bfloat162 l0 = __floats2bfloat162_rn(v.x - __bfloat162float(hx),
                                                      v.y - __bfloat162float(hy));
            __nv_bfloat162 l1 = __floats2bfloat162_rn(v.z - __bfloat162float(hz),
                                                      v.w - __bfloat162float(hw));
            uint2 pl; pl.x = *(uint32_t*)&l0; pl.y = *(uint32_t*)&l1;
            *(uint2*)&Bl[n * 40 + kg * 4] = pl;
        }
        __syncthreads();

#pragma unroll
        for (int ks = 0; ks < 2; ks++) {
            uint32_t ah0[4], ah1[4], al0[4], al1[4];
            uint32_t aoff = ((mw + (lane & 15)) * 40 + ks * 16 + (lane >> 4) * 8) * 2;
            ldsm4(ah0, sbAh + aoff);
            ldsm4(ah1, sbAh + aoff + 16 * 40 * 2);
            ldsm4(al0, sbAl + aoff);
            ldsm4(al1, sbAl + aoff + 16 * 40 * 2);
            uint32_t boff = ((nw + (lane & 7)) * 40 + ks * 16 + ((lane >> 3) & 1) * 8) * 2;
#pragma unroll
            for (int nt = 0; nt < 4; nt++) {
                uint32_t b0, b1;
                ldsm2(b0, b1, sbBh + boff + nt * 8 * 40 * 2);
                mma16816(cf[0][nt], ah0, b0, b1);
                mma16816(cf[1][nt], ah1, b0, b1);
                mma16816(cf[0][nt], al0, b0, b1);
                mma16816(cf[1][nt], al1, b0, b1);
                ldsm2(b0, b1, sbBl + boff + nt * 8 * 40 * 2);
                mma16816(cf[0][nt], ah0, b0, b1);
                mma16816(cf[1][nt], ah1, b0, b1);
            }
        }
        __syncthreads();
    }
#pragma unroll
    for (int mt = 0; mt < 2; mt++) {
        long long m = m0 + mw + mt * 16 + (lane >> 2);
#pragma unroll
        for (int nt = 0; nt < 4; nt++) {
            int n = n0 + nw + nt * 8 + (lane & 3) * 2;
            float bn0 = bias[n], bn1 = bias[n + 1];
            C[m * ldc + n]     = cf[mt][nt][0] + bn0;
            C[m * ldc + n + 1] = cf[mt][nt][1] + bn1;
            C[(m + 8) * ldc + n]     = cf[mt][nt][2] + bn0;
            C[(m + 8) * ldc + n + 1] = cf[mt][nt][3] + bn1;
        }
    }
}

// ============================================================
// Sequential sLSTM scan (R12 version, unchanged)
// ============================================================
__global__ void __launch_bounds__(512, 1)
scan_kernel(const float* __restrict__ Wcell, const float* __restrict__ Gx,
            float* __restrict__ seqh)
{
    extern __shared__ float2 ws2[];
    __shared__ float h_s[128], c_s[128], n_s[128], gates_s[512];
    int tid = threadIdx.x, b = blockIdx.x;

    ull wr2[48];
    {
        const float4* wrow = (const float4*)(Wcell + tid * 192 + 64);
#pragma unroll
        for (int c = 0; c < 24; c++) {
            float4 w = wrow[c];
            wr2[2 * c] = pk2(w.x, w.y);
            wr2[2 * c + 1] = pk2(w.z, w.w);
        }
    }
#pragma unroll
    for (int p = 0; p < 16; p++)
        ws2[p * 512 + tid] = make_float2(Wcell[tid * 192 + 160 + 2 * p],
                                         Wcell[tid * 192 + 160 + 2 * p + 1]);
    if (tid < 128) { h_s[tid] = 0.f; c_s[tid] = 0.f; n_s[tid] = 1.f; }
    __syncthreads();

    long long gbase = (long long)b * 512 * 512 + tid;
    long long hbase = (long long)b * 512 * 128;
    float gx = Gx[gbase];

    for (int t = 0; t < 512; t++) {
        float gx_next = (t < 511) ? Gx[gbase + (long long)(t + 1) * 512] : 0.f;
        ull a0 = pk2(gx, 0.f), a1 = pk2(0.f, 0.f);
#pragma unroll
        for (int c = 0; c < 24; c++) {
            float4 h4 = *(const float4*)&h_s[c * 4];
            a0 = fma2(wr2[2 * c],     pk2(h4.x, h4.y), a0);
            a1 = fma2(wr2[2 * c + 1], pk2(h4.z, h4.w), a1);
        }
#pragma unroll
        for (int c = 0; c < 8; c++) {
            float4 h4 = *(const float4*)&h_s[96 + c * 4];
            ull wA = *(const ull*)&ws2[(2 * c) * 512 + tid];
            ull wB = *(const ull*)&ws2[(2 * c + 1) * 512 + tid];
            a0 = fma2(wA, pk2(h4.x, h4.y), a0);
            a1 = fma2(wB, pk2(h4.z, h4.w), a1);
        }
        float2 f0 = up2(a0), f1 = up2(a1);
        gates_s[tid] = (f0.x + f0.y) + (f1.x + f1.y);
        __syncthreads();
        if (tid < 128) {
            float gi = gates_s[tid], gf = gates_s[tid + 128];
            float go = gates_s[tid + 256], gz = gates_s[tid + 384];
            float ii = __expf(fminf(fmaxf(gi, -5.f), 5.f));
            float ff = __expf(fminf(fmaxf(gf, -5.f), 5.f));
            float cc = fmaf(ff, c_s[tid], ii * __tanhf(gz));
            cc = fminf(fmaxf(cc, -1e6f), 1e6f);
            float nn = fminf(fmaxf(fmaf(ff, n_s[tid], ii), 1e-6f), 1e6f);
            float sig = __frcp_rn(1.f + __expf(-go));
            float hh = __fdividef(cc, nn) * sig;
            if (!isfinite(hh)) hh = 0.f;
            c_s[tid] = cc; n_s[tid] = nn; h_s[tid] = hh;
            seqh[hbase + (long long)t * 128 + tid] = hh;
        }
        __syncthreads();
        gx = gx_next;
    }
}

// ============================================================
// Fused flash attention v6 (R14 version, unchanged)
// ============================================================
__global__ void __launch_bounds__(256, 3)
flash_kernel(const float* __restrict__ qkv, float* __restrict__ av)
{
    extern __shared__ char smraw[];
    __nv_bfloat16* Qs = (__nv_bfloat16*)(smraw);
    __nv_bfloat16* Ks = (__nv_bfloat16*)(smraw + 10240);
    __nv_bfloat16* Vs = (__nv_bfloat16*)(smraw + 15360);
    __nv_bfloat16* Ps = (__nv_bfloat16*)(smraw + 20480);
    float* rowM = (float*)(smraw + 38912);
    float* rowL = (float*)(smraw + 39424);
    float* rowS = (float*)(smraw + 39936);

    int tid = threadIdx.x;
    int qt = blockIdx.x;
    int bh = blockIdx.y;
    int b = bh >> 2;
    int h = bh & 3;
    long long base = (long long)b * 512 * 384 + h * 32;
    int q0 = qt * 128;
    const float alpha = 0.25501398f;

    for (int idx = tid; idx < 1024; idx += 256) {
        int s = idx >> 3;
        int dg = idx & 7;
        float4 v = *(const float4*)&qkv[base + (long long)(q0 + s) * 384 + dg * 4];
        __nv_bfloat162 p0 = __floats2bfloat162_rn(v.x * alpha, v.y * alpha);
        __nv_bfloat162 p1 = __floats2bfloat162_rn(v.z * alpha, v.w * alpha);
        uint2 pk; pk.x = *(uint32_t*)&p0; pk.y = *(uint32_t*)&p1;
        *(uint2*)&Qs[s * 40 + dg * 4] = pk;
    }
    if (tid < 128) { rowM[tid] = -1e30f; rowL[tid] = 0.f; }
    __syncthreads();

    int w = tid >> 5;
    int lane = tid & 31;
    uint32_t sb = (uint32_t)__cvta_generic_to_shared(smraw);

    uint32_t aq0[4];
    uint32_t aq1[4];
    {
        uint32_t qaddr = sb + ((16 * w + (lane & 15)) * 40 + (lane >> 4) * 8) * 2;
        ldsm4(aq0, qaddr);
        ldsm4(aq1, qaddr + 32);
    }

    int qA = 16 * w + (lane >> 2);
    int qB = qA + 8;
    float of[4][4];
#pragma unroll
    for (int i = 0; i < 4; i++) {
        of[i][0] = 0.f; of[i][1] = 0.f; of[i][2] = 0.f; of[i][3] = 0.f;
    }

    for (int kt = 0; kt < 8; kt++) {
        int kbase = kt * 64;
        for (int idx = tid; idx < 512; idx += 256) {
            int s = idx >> 3;
            int dg = idx & 7;
            long long grow = base + (long long)(kbase + s) * 384 + dg * 4;
            float4 kv = *(const float4*)&qkv[grow + 128];
            float4 vv = *(const float4*)&qkv[grow + 256];
            __nv_bfloat162 k0 = __floats2bfloat162_rn(kv.x, kv.y);
            __nv_bfloat162 k1 = __floats2bfloat162_rn(kv.z, kv.w);
            uint2 kk; kk.x = *(uint32_t*)&k0; kk.y = *(uint32_t*)&k1;
            *(uint2*)&Ks[s * 40 + dg * 4] = kk;
            __nv_bfloat162 v0 = __floats2bfloat162_rn(vv.x, vv.y);
            __nv_bfloat162 v1 = __floats2bfloat162_rn(vv.z, vv.w);
            uint2 vp; vp.x = *(uint32_t*)&v0; vp.y = *(uint32_t*)&v1;
            *(uint2*)&Vs[s * 40 + dg * 4] = vp;
        }
        __syncthreads();

        float cf[8][4];
#pragma unroll
        for (int nt = 0; nt < 8; nt++) {
            cf[nt][0] = 0.f; cf[nt][1] = 0.f; cf[nt][2] = 0.f; cf[nt][3] = 0.f;
        }
        uint32_t kaddr0 = sb + 10240 + ((lane & 7) * 40 + ((lane >> 3) & 1) * 8) * 2;
#pragma unroll
        for (int nt = 0; nt < 8; nt++) {
            uint32_t addr = kaddr0 + nt * 640;
            uint32_t b0, b1;
            ldsm2(b0, b1, addr);
            mma16816(cf[nt], aq0, b0, b1);
            ldsm2(b0, b1, addr + 32);
            mma16816(cf[nt], aq1, b0, b1);
        }

        float moA = rowM[qA];
        float moB = rowM[qB];
        float mxA = cf[0][0];
        float mxB = cf[0][2];
#pragma unroll
        for (int nt = 0; nt < 8; nt++) {
            mxA = fmaxf(mxA, fmaxf(cf[nt][0], cf[nt][1]));
            mxB = fmaxf(mxB, fmaxf(cf[nt][2], cf[nt][3]));
        }
        mxA = fmaxf(mxA, __shfl_xor_sync(0xffffffffu, mxA, 1));
        mxA = fmaxf(mxA, __shfl_xor_sync(0xffffffffu, mxA, 2));
        mxB = fmaxf(mxB, __shfl_xor_sync(0xffffffffu, mxB, 1));
        mxB = fmaxf(mxB, __shfl_xor_sync(0xffffffffu, mxB, 2));
        float mnA = fmaxf(moA, mxA);
        float mnB = fmaxf(moB, mxB);
        float sumA = 0.f, sumB = 0.f;
        int colo = (lane & 3) * 2;
#pragma unroll
        for (int nt = 0; nt < 8; nt++) {
            float e0 = ex2f(cf[nt][0] - mnA);
            float e1 = ex2f(cf[nt][1] - mnA);
            float e2 = ex2f(cf[nt][2] - mnB);
            float e3 = ex2f(cf[nt][3] - mnB);
            sumA += e0 + e1;
            sumB += e2 + e3;
            __nv_bfloat162 pa = __floats2bfloat162_rn(e0, e1);
            __nv_bfloat162 pb = __floats2bfloat162_rn(e2, e3);
            *(uint32_t*)&Ps[qA * 72 + nt * 8 + colo] = *(uint32_t*)&pa;
            *(uint32_t*)&Ps[qB * 72 + nt * 8 + colo] = *(uint32_t*)&pb;
        }
        sumA += __shfl_xor_sync(0xffffffffu, sumA, 1);
        sumA += __shfl_xor_sync(0xffffffffu, sumA, 2);
        sumB += __shfl_xor_sync(0xffffffffu, sumB, 1);
        sumB += __shfl_xor_sync(0xffffffffu, sumB, 2);
        if ((lane & 3) == 0) {
            float scA = ex2f(moA - mnA);
            float scB = ex2f(moB - mnB);
            rowS[qA] = scA; rowM[qA] = mnA; rowL[qA] = rowL[qA] * scA + sumA;
            rowS[qB] = scB; rowM[qB] = mnB; rowL[qB] = rowL[qB] * scB + sumB;
        }
        __syncwarp();

        {
            float scA = rowS[qA];
            float scB = rowS[qB];
#pragma unroll
            for (int i = 0; i < 4; i++) {
                of[i][0] *= scA; of[i][1] *= scA;
                of[i][2] *= scB; of[i][3] *= scB;
            }
        }
        uint32_t paddr0 = sb + 20480 + ((16 * w + (lane & 15)) * 72 + (lane >> 4) * 8) * 2;
        uint32_t vaddr0 = sb + 15360 + ((lane & 15) * 40) * 2;
#pragma unroll
        for (int ks = 0; ks < 4; ks++) {
            uint32_t ap[4];
            ldsm4(ap, paddr0 + ks * 32);
#pragma unroll
            for (int nt2 = 0; nt2 < 4; nt2++) {
                uint32_t b0, b1;
                ldsm2t(b0, b1, vaddr0 + ks * 1280 + nt2 * 16);
                mma16816(of[nt2], ap, b0, b1);
            }
        }
        __syncthreads();
    }

    {
        float iA = 1.f / rowL[qA];
        float iB = 1.f / rowL[qB];
        long long orA = (long long)(b * 512 + q0 + qA) * 128 + h * 32 + (lane & 3) * 2;
        long long orB = orA + 8LL * 128;
#pragma unroll
        for (int nt2 = 0; nt2 < 4; nt2++) {
            float2 ra; ra.x = of[nt2][0] * iA; ra.y = of[nt2][1] * iA;
            float2 rb; rb.x = of[nt2][2] * iB; rb.y = of[nt2][3] * iB;
            *(float2*)&av[orA + nt2 * 8] = ra;
            *(float2*)&av[orB + nt2 * 8] = rb;
        }
    }
}

// ============================================================
// Reductions (128-thread blocks)
// ============================================================
__device__ __forceinline__ float2 blockReduce2(float a, float b, float2* sh)
{
#pragma unroll
    for (int o = 16; o; o >>= 1) {
        a += __shfl_xor_sync(0xffffffffu, a, o);
        b += __shfl_xor_sync(0xffffffffu, b, o);
    }
    int w = threadIdx.x >> 5;
    if ((threadIdx.x & 31) == 0) sh[w] = make_float2(a, b);
    __syncthreads();
    float2 r;
    r.x = sh[0].x + sh[1].x + sh[2].x + sh[3].x;
    r.y = sh[0].y + sh[1].y + sh[2].y + sh[3].y;
    __syncthreads();
    return r;
}

__global__ void zero_ctx_kernel(float* ctx) { ctx[blockIdx.x * 128 + threadIdx.x] = 0.f; }

__global__ void ln_mean_kernel(const float* __restrict__ seqh, const float* __restrict__ ao,
                               const float* __restrict__ g, const float* __restrict__ bln,
                               float* __restrict__ ctx)
{
    __shared__ float2 sh[4];
    int b = blockIdx.x >> 5, chunk = blockIdx.x & 31;
    int tid = threadIdx.x;
    float acc = 0.f;
    for (int r = 0; r < 16; r++) {
        long long row = ((long long)b * 512 + chunk * 16 + r) * 128;
        float y = seqh[row + tid] + ao[row + tid];
        float2 ss = blockReduce2(y, y * y, sh);
        float mean = ss.x * (1.f / 128.f);
        float var = ss.y * (1.f / 128.f) - mean * mean;
        acc += g[tid] * (y - mean) * rsqrtf(var + 1e-5f) + bln[tid];
    }
    atomicAdd(&ctx[b * 128 + tid], acc);
}

__global__ void heads_kernel(const float* __restrict__ ctx, const float* __restrict__ info,
    const float* __restrict__ Wa1, const float* __restrict__ ba1,
    const float* __restrict__ lna_g, const float* __restrict__ lna_b,
    const float* __restrict__ Wa2, const float* __restrict__ ba2,
    const float* __restrict__ Wc1, const float* __restrict__ bc1,
    const float* __restrict__ lnc_g, const float* __restrict__ lnc_b,
    const float* __restrict__ Wc2, const float* __restrict__ bc2,
    float* __restrict__ out)
{
    __shared__ float comb[144];
    __shared__ float ra[128], rc[128];
    __shared__ float logit[3];
    __shared__ float2 sh[4];
    int b = blockIdx.x, tid = threadIdx.x;
    comb[tid] = ctx[b * 128 + tid] * (1.f / 512.f);
    if (tid < 16) comb[128 + tid] = (tid < 13) ? info[b * 13 + tid] : 0.f;
    __syncthreads();

    float sa = ba1[tid], sc = bc1[tid];
    for (int k = 0; k < 141; k++) {
        sa = fmaf(Wa1[tid * 141 + k], comb[k], sa);
        sc = fmaf(Wc1[tid * 141 + k], comb[k], sc);
    }
    float2 r2 = blockReduce2(sa, sa * sa, sh);
    float ma = r2.x * (1.f / 128.f), va = r2.y * (1.f / 128.f) - ma * ma;
    ra[tid] = fmaxf(lna_g[tid] * (sa - ma) * rsqrtf(va + 1e-5f) + lna_b[tid], 0.f);
    r2 = blockReduce2(sc, sc * sc, sh);
    float mc = r2.x * (1.f / 128.f), vc = r2.y * (1.f / 128.f) - mc * mc;
    rc[tid] = fmaxf(lnc_g[tid] * (sc - mc) * rsqrtf(vc + 1e-5f) + lnc_b[tid], 0.f);
    __syncthreads();

    if (tid < 3) {
        float l = ba2[tid];
        for (int k = 0; k < 128; k++) l = fmaf(Wa2[tid * 128 + k], ra[k], l);
        logit[tid] = l;
    }
    float2 vv = blockReduce2(rc[tid] * Wc2[tid], 0.f, sh);
    if (tid == 0) out[192 + b] = vv.x + bc2[0];
    __syncthreads();
    if (tid == 0) {
        float m = fmaxf(logit[0], fmaxf(logit[1], logit[2]));
        float e0 = expf(logit[0] - m), e1 = expf(logit[1] - m), e2 = expf(logit[2] - m);
        float inv = 1.f / (e0 + e1 + e2);
        out[b * 3 + 0] = e0 * inv;
        out[b * 3 + 1] = e1 * inv;
        out[b * 3 + 2] = e2 * inv;
    }
}

// ============================================================
extern "C" void kernel_launch(void* const* d_in, const int* in_sizes, int n_in,
                              void* d_out, int out_size)
{
    const float* x      = (const float*)d_in[0];
    const float* info   = (const float*)d_in[1];
    const float* W_cell = (const float*)d_in[2];
    const float* b_cell = (const float*)d_in[3];
    const float* Wqkv   = (const float*)d_in[4];
    const float* bqkv   = (const float*)d_in[5];
    const float* Wo     = (const float*)d_in[6];
    const float* bo     = (const float*)d_in[7];
    const float* ln_g   = (const float*)d_in[8];
    const float* ln_b   = (const float*)d_in[9];
    const float* Wa1    = (const float*)d_in[10];
    const float* ba1    = (const float*)d_in[11];
    const float* lna_g  = (const float*)d_in[12];
    const float* lna_b  = (const float*)d_in[13];
    const float* Wa2    = (const float*)d_in[14];
    const float* ba2    = (const float*)d_in[15];
    const float* Wc1    = (const float*)d_in[16];
    const float* bc1    = (const float*)d_in[17];
    const float* lnc_g  = (const float*)d_in[18];
    const float* lnc_b  = (const float*)d_in[19];
    const float* Wc2    = (const float*)d_in[20];
    const float* bc2    = (const float*)d_in[21];
    float* out = (float*)d_out;
    (void)in_sizes; (void)n_in; (void)out_size;

    float *pGx, *pSeqh, *pQkv, *pAv, *pAo, *pCtx;
    cudaGetSymbolAddress((void**)&pGx, g_Gx);
    cudaGetSymbolAddress((void**)&pSeqh, g_seqh);
    cudaGetSymbolAddress((void**)&pQkv, g_qkv);
    cudaGetSymbolAddress((void**)&pAv, g_av);
    cudaGetSymbolAddress((void**)&pAo, g_attnout);
    cudaGetSymbolAddress((void**)&pCtx, g_ctx);

    cudaFuncSetAttribute(scan_kernel, cudaFuncAttributeMaxDynamicSharedMemorySize, 72 * 1024);
    cudaFuncSetAttribute(flash_kernel, cudaFuncAttributeMaxDynamicSharedMemorySize, 40448);

    // 1) Gx = x @ Wcell[:, :64]^T + b_cell            (bf16 TC, dual split)
    gemm_nt_bf16_split3<<<dim3(8, 256), 256>>>(x, 64, W_cell, 192, b_cell, pGx, 512, 64);

    // 2) sequential scan -> seqh
    scan_kernel<<<64, 512, 16 * 512 * sizeof(float2)>>>(W_cell, pGx, pSeqh);

    // 3) qkv = seqh @ Wqkv^T + bqkv                   (bf16 TC, weight-split)
    gemm_nt_bf16<<<dim3(6, 256), 256>>>(pSeqh, 128, Wqkv, 128, bqkv, pQkv, 384, 128);

    // 4) fused attention v6 (bf16 tensor cores)
    flash_kernel<<<dim3(4, 256), 256, 40448>>>(pQkv, pAv);

    // 5) attn_out = av @ Wo^T + bo                    (bf16 TC, weight-split)
    gemm_nt_bf16<<<dim3(2, 256), 256>>>(pAv, 128, Wo, 128, bo, pAo, 128, 128);

    // 6) context = mean_s LN(seqh + attn_out)
    zero_ctx_kernel<<<64, 128>>>(pCtx);
    ln_mean_kernel<<<2048, 128>>>(pSeqh, pAo, ln_g, ln_b, pCtx);

    // 7) heads
    heads_kernel<<<64, 128>>>(pCtx, info, Wa1, ba1, lna_g, lna_b, Wa2, ba2,
                              Wc1, bc1, lnc_g, lnc_b, Wc2, bc2, out);
}